// round 4
// baseline (speedup 1.0000x reference)
#include <cuda_runtime.h>

#define TN 32768
#define TLOOP 32799
#define NCHUNK 2050
#define NSTEPS (NCHUNK*16)   /* 32800 */
#define NBC 14
#define NACL 10
#define NACG 35
#define KACN 52
#define K0 20
#define K1 32
#define PADL 50              /* (K0-1)+(K1-1) */
#define XPLEN (TN + PADL)    /* 32818 */
#define RELSTRIDE 32832

__device__ float g_xp[XPLEN];
__device__ float g_drive[NSTEPS*NBC];
__device__ float g_rel[2*NBC*RELSTRIDE];
__device__ float g_kbc[NBC*K0];
__device__ float g_kglu[K1];

__device__ __forceinline__ float ftanh(float x){
    float y; asm("tanh.approx.f32 %0, %1;" : "=f"(y) : "f"(x)); return y;
}
__device__ __forceinline__ float fex2(float x){
    float y; asm("ex2.approx.f32 %0, %1;" : "=f"(y) : "f"(x)); return y;
}
__device__ __forceinline__ float frcp(float x){
    float y; asm("rcp.approx.f32 %0, %1;" : "=f"(y) : "f"(x)); return y;
}

// double-exponential AC kernel -> IIR coefficients (exact FIR-equivalent with
// truncation correction): kern(L) = A*r1^L - B*r2^L (L=0 newest), L2-normalized
__device__ __forceinline__ void ac_coef(float ltr, float ltd,
    float &A, float &B, float &r1, float &r2, float &c1, float &c2){
    float tr = expf(ltr), td = expf(ltd);
    float beta = (td + tr) / (td * tr);
    float n2 = 0.f;
    for (int k = 0; k < KACN; k++){
        float t = 0.8f - (float)k * (1.0f/64.0f);
        float v = expf(-t/td) - expf(-beta*t);
        n2 = fmaf(v, v, n2);
    }
    float inv = 1.0f / sqrtf(n2);
    const float c0 = 0.8f - 51.0f*(1.0f/64.0f);
    A  = expf(-c0/td) * inv;
    B  = expf(-beta*c0) * inv;
    r1 = expf(-1.0f/(64.0f*td));
    r2 = expf(-beta*(1.0f/64.0f));
    c1 = expf(-0.8125f/td);        /* r1^52 */
    c2 = expf(-beta*0.8125f);      /* r2^52 */
}

// ---------------- setup: BC biphasic kernels + iGluSnFR kernel ----------------
__global__ void setup_kernel(const float* __restrict__ lks){
    int t = threadIdx.x;
    if (t < NBC){
        float speed = expf(lks[t]);
        float ct = (t < 5) ? -1.0f : 1.0f;
        float vals[K0]; float n2 = 0.f;
        #pragma unroll
        for (int j = 0; j < K0; j++){
            float ts = (float)j * (1.0f/64.0f) * speed;
            float a = ts / 0.05f, b = ts / 0.1f;
            float v = a*a*expf(-a) - 0.8f*b*b*expf(-b);
            v *= ct;
            vals[j] = v; n2 += v*v;
        }
        float inv = 1.0f / sqrtf(n2);
        #pragma unroll
        for (int j = 0; j < K0; j++) g_kbc[t*K0+j] = vals[j]*inv;
    }
    if (t == 32){
        float vals[K1]; float s = 0.f;
        #pragma unroll
        for (int j = 0; j < K1; j++){
            float tg = (float)j * (1.0f/64.0f);
            float v = (1.0f - expf(-tg/0.02f)) * expf(-tg/0.1f);
            vals[j] = v; s += v;
        }
        #pragma unroll
        for (int j = 0; j < K1; j++) g_kglu[j] = vals[j]/s;
    }
}

// ---------------- stimulus affine + edge padding ----------------
__global__ void xp_kernel(const float* __restrict__ x,
                          const float* __restrict__ sb,
                          const float* __restrict__ ss){
    int i = blockIdx.x*blockDim.x + threadIdx.x;
    if (i >= XPLEN) return;
    float es = expf(ss[0]); float b = sb[0];
    int s = i - PADL; if (s < 0) s = 0;
    g_xp[i] = x[s]*es + b;
}

// ---------------- per-BC 20-tap FIR -> drive[NSTEPS][NBC] ----------------
__global__ void drive_kernel(){
    __shared__ float skb[NBC*K0];
    int tid = threadIdx.x;
    for (int i = tid; i < NBC*K0; i += blockDim.x) skb[i] = g_kbc[i];
    __syncthreads();
    int n = blockIdx.x*blockDim.x + tid;
    if (n >= NSTEPS) return;
    if (n >= TLOOP){
        #pragma unroll
        for (int c = 0; c < NBC; c++) g_drive[n*NBC+c] = 0.f;
        return;
    }
    float xw[K0];
    #pragma unroll
    for (int j = 0; j < K0; j++) xw[j] = g_xp[n + j];
    #pragma unroll
    for (int c = 0; c < NBC; c++){
        float a0 = 0.f, a1 = 0.f;
        #pragma unroll
        for (int j = 0; j < K0; j++){
            float w = skb[c*K0+j];
            float v = xw[K0-1-j];
            if (j & 1) a1 = fmaf(w, v, a1); else a0 = fmaf(w, v, a0);
        }
        g_drive[n*NBC+c] = a0 + a1;
    }
}

// ---------------- the sequential scan: 2 blocks (pathways) x 1 warp ----------------
__global__ void __launch_bounds__(32,1) scan_kernel(
    const float* __restrict__ P_sigoff, const float* __restrict__ P_lslope,
    const float* __restrict__ P_lp01,  const float* __restrict__ P_lp12,
    const float* __restrict__ P_lipc,  const float* __restrict__ P_lrrpc,
    const float* __restrict__ P_ipst,  const float* __restrict__ P_rrpst,
    const float* __restrict__ P_laclbc, const float* __restrict__ P_lbcacl,
    const float* __restrict__ P_acltr, const float* __restrict__ P_acltd,
    const float* __restrict__ P_aclsl, const float* __restrict__ P_aclof,
    const float* __restrict__ P_lacgbc, const float* __restrict__ P_lbcacg,
    const float* __restrict__ P_acgtr, const float* __restrict__ P_acgtd,
    const float* __restrict__ P_acgsl, const float* __restrict__ P_acgof,
    const float* __restrict__ P_laclacg, const float* __restrict__ P_bcnoff)
{
    const int path = blockIdx.x;
    const int l = threadIdx.x;
    __shared__ float ringA[NACL*53];
    __shared__ float ringG[NACG*53];
    __shared__ float dbuf[2][16*NBC];
    __shared__ __align__(16) float sm_tvG[36];
    for (int i = l; i < NACL*53; i += 32) ringA[i] = 0.f;
    for (int i = l; i < NACG*53; i += 32) ringG[i] = 0.f;
    { int i = l; if (i < 36) sm_tvG[i] = 0.f; if (i+32 < 36) sm_tvG[i+32] = 0.f; }

    // ---- BC role (lane < 14): exp-form final sigmoid, log2e+slope pre-folded ----
    float cP=0.f, mBC=0.f, c_p01=0.f, c_p12=0.f, c_ipcap=0.f, c_irrp=0.f;
    float ip=0.f, rrp=0.f;
    float wfbAE[10], wfbGE[36];
    #pragma unroll
    for (int j = 0; j < 10; j++) wfbAE[j] = 0.f;
    #pragma unroll
    for (int j = 0; j < 36; j++) wfbGE[j] = 0.f;
    if (l < NBC){
        float off   = P_sigoff[l] + (path ? P_bcnoff[l] : 0.f);
        float slope = expf(P_lslope[l]);
        mBC = -slope * 1.44269504f;          /* exp(-z) = 2^(mBC * total) */
        c_p01   = expf(P_lp01[l]);
        c_p12   = expf(P_lp12[l]);
        c_ipcap = expf(P_lipc[l]);
        float rc = expf(P_lrrpc[l]);
        c_irrp = 1.0f / rc;
        ip  = c_ipcap / (1.0f + expf(-P_ipst[l]));
        rrp = rc      / (1.0f + expf(-P_rrpst[l]));
        float sA = 0.f, sG = 0.f;
        #pragma unroll
        for (int j = 0; j < NACL; j++){
            float w = -expf(P_laclbc[l*NACL+j]);
            sA += w; wfbAE[j] = 0.5f*mBC*w;
        }
        if (path){
            #pragma unroll
            for (int j = 0; j < NACG; j++){
                float w = -expf(P_lacgbc[l*NACG+j]);
                sG += w; wfbGE[j] = 0.5f*mBC*w;
            }
        }
        cP = mBC*(0.5f*(sA+sG) - off);
    }

    // ---- ACL role (lane < 10): tanh-form, half-slope pre-folded into state ----
    float kA1=0.f,kA2=0.f,aR1=1.f,aR2=1.f,kA1c=0.f,kA2c=0.f,caA=0.f,dkA=0.f;
    float wyA[NBC];
    #pragma unroll
    for (int j = 0; j < NBC; j++) wyA[j] = 0.f;
    if (l < NACL){
        float A,B,r1,r2,c1,c2;
        ac_coef(P_acltr[l], P_acltd[l], A,B,r1,r2,c1,c2);
        float ha = 0.5f*expf(P_aclsl[l]);
        kA1 = ha*A; kA2 = ha*B; aR1=r1; aR2=r2;
        kA1c = kA1*c1; kA2c = kA2*c2;
        caA = -ha*P_aclof[l];
        dkA = kA1 - kA2;
        #pragma unroll
        for (int j = 0; j < NBC; j++) wyA[j] = expf(P_lbcacl[l*NBC+j]);
    }

    // ---- ACG roles (pathway 2 only): g = lane (0..31), h = lane+32 (lanes 0..2) ----
    float kG1=0.f,kG2=0.f,gR1=1.f,gR2=1.f,kG1c=0.f,kG2c=0.f,cgG=0.f,dkG=0.f;
    float kH1=0.f,kH2=0.f,hR1=1.f,hR2=1.f,kH1c=0.f,kH2c=0.f,cgH=0.f,dkH=0.f;
    float wGaE[10], wHaE[10], wyG[NBC], wyH[NBC];
    #pragma unroll
    for (int j = 0; j < 10; j++){ wGaE[j]=0.f; wHaE[j]=0.f; }
    #pragma unroll
    for (int j = 0; j < NBC; j++){ wyG[j]=0.f; wyH[j]=0.f; }
    if (path){
        float A,B,r1,r2,c1,c2;
        ac_coef(P_acgtr[l], P_acgtd[l], A,B,r1,r2,c1,c2);
        float hg = 0.5f*expf(P_acgsl[l]);
        kG1 = hg*A; kG2 = hg*B; gR1=r1; gR2=r2;
        kG1c = kG1*c1; kG2c = kG2*c2;
        float sw = 0.f;
        #pragma unroll
        for (int j = 0; j < NACL; j++){
            float w = -expf(P_laclacg[l*NACL+j]);
            sw += w; wGaE[j] = hg*0.5f*w;
        }
        cgG = hg*(0.5f*sw - P_acgof[l]);
        dkG = kG1 - kG2;
        #pragma unroll
        for (int j = 0; j < NBC; j++) wyG[j] = expf(P_lbcacg[l*NBC+j]);
        if (l < 3){
            int h = l + 32;
            ac_coef(P_acgtr[h], P_acgtd[h], A,B,r1,r2,c1,c2);
            float hh = 0.5f*expf(P_acgsl[h]);
            kH1 = hh*A; kH2 = hh*B; hR1=r1; hR2=r2;
            kH1c = kH1*c1; kH2c = kH2*c2;
            float swh = 0.f;
            #pragma unroll
            for (int j = 0; j < NACL; j++){
                float w = -expf(P_laclacg[h*NACL+j]);
                swh += w; wHaE[j] = hh*0.5f*w;
            }
            cgH = hh*(0.5f*swh - P_acgof[h]);
            dkH = kH1 - kH2;
            #pragma unroll
            for (int j = 0; j < NBC; j++) wyH[j] = expf(P_lbcacg[h*NBC+j]);
        }
    }
    __syncwarp();

    float* relrow = g_rel + (path*NBC + ((l < NBC) ? l : 0))*RELSTRIDE;
    float A1=0.f,A2=0.f,G1=0.f,G2=0.f,H1=0.f,H2=0.f;
    /* carried pre-activations (state as of "now") */
    float cvA = caA, baseG = cgG, baseH = cgH;
    int ri = 0;

    float fd0,fd1,fd2,fd3,fd4,fd5,fd6;
#define LOADCHUNK(k) do{ const float* _p = g_drive + (k)*224 + l; \
        fd0=_p[0]; fd1=_p[32]; fd2=_p[64]; fd3=_p[96]; fd4=_p[128]; fd5=_p[160]; fd6=_p[192]; }while(0)
#define STORECHUNK(bi) do{ float* _q = dbuf[bi] + l; \
        _q[0]=fd0; _q[32]=fd1; _q[64]=fd2; _q[96]=fd3; _q[128]=fd4; _q[160]=fd5; _q[192]=fd6; }while(0)

    LOADCHUNK(0); STORECHUNK(0); LOADCHUNK(1);
    __syncwarp();

    if (path == 0){
        // ---------- LNR pathway: ACL feedback only ----------
        for (int c = 0; c < NCHUNK; c++){
            int cur = c & 1;
            STORECHUNK(cur^1);
            int nk = (c+2 < NCHUNK) ? (c+2) : (NCHUNK-1);
            LOADCHUNK(nk);
            __syncwarp();
            const float* db = dbuf[cur];
            int tbase = c*16;
            #pragma unroll 4
            for (int i = 0; i < 16; i++){
                /* off-chain */
                float yoA = (l < NACL) ? ringA[l*53+ri] : 0.f;
                float xi  = (l < NBC) ? db[i*NBC + l] : 0.f;
                float fbBase = fmaf(mBC, xi, cP);
                float t12 = c_p12*ip*(1.0f - rrp*c_irrp);
                float ip_n = ip + c_p01*(c_ipcap - ip) - t12;
                float rrp_m = rrp + t12;
                float bA1 = fmaf(-kA1c, yoA, aR1*A1);
                float bA2 = fmaf(-kA2c, yoA, aR2*A2);
                float bD  = (bA1 - bA2) + caA;
                /* chain */
                float tvA = ftanh(cvA);
                float fb0 = fbBase, fb1 = 0.f;
                #pragma unroll
                for (int j = 0; j < NACL; j++){
                    float v = __shfl_sync(0xffffffffu, tvA, j);
                    if (j & 1) fb1 = fmaf(wfbAE[j], v, fb1);
                    else       fb0 = fmaf(wfbAE[j], v, fb0);
                }
                float e = fex2(fb0 + fb1);
                float relv = rrp * frcp(1.0f + e);
                ip = ip_n; rrp = rrp_m - relv;
                if (l < NBC) relrow[tbase+i] = relv;
                float y0 = 0.f, y1 = 0.f, y2 = 0.f, y3 = 0.f;
                #pragma unroll
                for (int j = 0; j < NBC; j++){
                    float v = __shfl_sync(0xffffffffu, relv, j);
                    if ((j&3)==0) y0 = fmaf(wyA[j], v, y0);
                    else if ((j&3)==1) y1 = fmaf(wyA[j], v, y1);
                    else if ((j&3)==2) y2 = fmaf(wyA[j], v, y2);
                    else y3 = fmaf(wyA[j], v, y3);
                }
                float yA = (y0+y1)+(y2+y3);
                cvA = fmaf(dkA, yA, bD);
                if (l < NACL) ringA[l*53+ri] = yA;
                A1 = fmaf(kA1, yA, bA1);
                A2 = fmaf(kA2, yA, bA2);
                ri = (ri == KACN-1) ? 0 : ri+1;
            }
            __syncwarp();
        }
    } else {
        // ---------- BCN pathway: ACL + ACG feedback ----------
        const float4* SG = (const float4*)sm_tvG;
        for (int c = 0; c < NCHUNK; c++){
            int cur = c & 1;
            STORECHUNK(cur^1);
            int nk = (c+2 < NCHUNK) ? (c+2) : (NCHUNK-1);
            LOADCHUNK(nk);
            __syncwarp();
            const float* db = dbuf[cur];
            int tbase = c*16;
            #pragma unroll 2
            for (int i = 0; i < 16; i++){
                /* ---- off-chain top work ---- */
                float yoA = (l < NACL) ? ringA[l*53+ri] : 0.f;
                float yoG = ringG[l*53+ri];
                float yoH = (l < 3) ? ringG[(l+32)*53+ri] : 0.f;
                float xi  = (l < NBC) ? db[i*NBC + l] : 0.f;
                float fbBase = fmaf(mBC, xi, cP);
                float t12 = c_p12*ip*(1.0f - rrp*c_irrp);
                float ip_n = ip + c_p01*(c_ipcap - ip) - t12;
                float rrp_m = rrp + t12;
                float bA1 = fmaf(-kA1c, yoA, aR1*A1);
                float bA2 = fmaf(-kA2c, yoA, aR2*A2);
                float bDA = (bA1 - bA2) + caA;
                float bG1 = fmaf(-kG1c, yoG, gR1*G1);
                float bG2 = fmaf(-kG2c, yoG, gR2*G2);
                float bDG = (bG1 - bG2) + cgG;
                float bH1 = fmaf(-kH1c, yoH, hR1*H1);
                float bH2 = fmaf(-kH2c, yoH, hR2*H2);
                float bDH = (bH1 - bH2) + cgH;
                /* ---- stage 1: ACL tanh + shfl broadcast ---- */
                float tvA = ftanh(cvA);
                float tA0 = __shfl_sync(0xffffffffu, tvA, 0);
                float tA1 = __shfl_sync(0xffffffffu, tvA, 1);
                float tA2 = __shfl_sync(0xffffffffu, tvA, 2);
                float tA3 = __shfl_sync(0xffffffffu, tvA, 3);
                float tA4 = __shfl_sync(0xffffffffu, tvA, 4);
                float tA5 = __shfl_sync(0xffffffffu, tvA, 5);
                float tA6 = __shfl_sync(0xffffffffu, tvA, 6);
                float tA7 = __shfl_sync(0xffffffffu, tvA, 7);
                float tA8 = __shfl_sync(0xffffffffu, tvA, 8);
                float tA9 = __shfl_sync(0xffffffffu, tvA, 9);
                /* ---- stage 2: ACG pre-activations (3 accum each) ---- */
                float pg0 = baseG, pg1 = 0.f, pg2 = 0.f;
                pg0 = fmaf(wGaE[0], tA0, pg0); pg1 = fmaf(wGaE[1], tA1, pg1); pg2 = fmaf(wGaE[2], tA2, pg2);
                pg0 = fmaf(wGaE[3], tA3, pg0); pg1 = fmaf(wGaE[4], tA4, pg1); pg2 = fmaf(wGaE[5], tA5, pg2);
                pg0 = fmaf(wGaE[6], tA6, pg0); pg1 = fmaf(wGaE[7], tA7, pg1); pg2 = fmaf(wGaE[8], tA8, pg2);
                pg0 = fmaf(wGaE[9], tA9, pg0);
                float ph0 = baseH, ph1 = 0.f, ph2 = 0.f;
                ph0 = fmaf(wHaE[0], tA0, ph0); ph1 = fmaf(wHaE[1], tA1, ph1); ph2 = fmaf(wHaE[2], tA2, ph2);
                ph0 = fmaf(wHaE[3], tA3, ph0); ph1 = fmaf(wHaE[4], tA4, ph1); ph2 = fmaf(wHaE[5], tA5, ph2);
                ph0 = fmaf(wHaE[6], tA6, ph0); ph1 = fmaf(wHaE[7], tA7, ph1); ph2 = fmaf(wHaE[8], tA8, ph2);
                ph0 = fmaf(wHaE[9], tA9, ph0);
                float tvG = ftanh(pg0 + (pg1 + pg2));
                float tvH = ftanh(ph0 + (ph1 + ph2));
                sm_tvG[l] = tvG;
                if (l < 3) sm_tvG[32+l] = tvH;
                /* ACL->BC partial sums overlap the ACG stage (independent of tvG) */
                float ae0 = wfbAE[0]*tA0, ae1 = wfbAE[1]*tA1, ae2 = wfbAE[2]*tA2, ae3 = wfbAE[3]*tA3;
                ae0 = fmaf(wfbAE[4], tA4, ae0); ae1 = fmaf(wfbAE[5], tA5, ae1);
                ae2 = fmaf(wfbAE[6], tA6, ae2); ae3 = fmaf(wfbAE[7], tA7, ae3);
                ae0 = fmaf(wfbAE[8], tA8, ae0); ae1 = fmaf(wfbAE[9], tA9, ae1);
                __syncwarp();
                /* ---- stage 3: BC pre-activation (36 taps via vec4 smem broadcast) ---- */
                float4 q0=SG[0],q1=SG[1],q2=SG[2],q3=SG[3],q4=SG[4],q5=SG[5],q6=SG[6],q7=SG[7],q8=SG[8];
                float a0 = fbBase, a1=0.f,a2=0.f,a3=0.f, a4=ae0,a5=ae1,a6=ae2,a7=ae3;
                a0=fmaf(wfbGE[0],q0.x,a0); a1=fmaf(wfbGE[1],q0.y,a1); a2=fmaf(wfbGE[2],q0.z,a2); a3=fmaf(wfbGE[3],q0.w,a3);
                a4=fmaf(wfbGE[4],q1.x,a4); a5=fmaf(wfbGE[5],q1.y,a5); a6=fmaf(wfbGE[6],q1.z,a6); a7=fmaf(wfbGE[7],q1.w,a7);
                a0=fmaf(wfbGE[8],q2.x,a0); a1=fmaf(wfbGE[9],q2.y,a1); a2=fmaf(wfbGE[10],q2.z,a2); a3=fmaf(wfbGE[11],q2.w,a3);
                a4=fmaf(wfbGE[12],q3.x,a4); a5=fmaf(wfbGE[13],q3.y,a5); a6=fmaf(wfbGE[14],q3.z,a6); a7=fmaf(wfbGE[15],q3.w,a7);
                a0=fmaf(wfbGE[16],q4.x,a0); a1=fmaf(wfbGE[17],q4.y,a1); a2=fmaf(wfbGE[18],q4.z,a2); a3=fmaf(wfbGE[19],q4.w,a3);
                a4=fmaf(wfbGE[20],q5.x,a4); a5=fmaf(wfbGE[21],q5.y,a5); a6=fmaf(wfbGE[22],q5.z,a6); a7=fmaf(wfbGE[23],q5.w,a7);
                a0=fmaf(wfbGE[24],q6.x,a0); a1=fmaf(wfbGE[25],q6.y,a1); a2=fmaf(wfbGE[26],q6.z,a2); a3=fmaf(wfbGE[27],q6.w,a3);
                a4=fmaf(wfbGE[28],q7.x,a4); a5=fmaf(wfbGE[29],q7.y,a5); a6=fmaf(wfbGE[30],q7.z,a6); a7=fmaf(wfbGE[31],q7.w,a7);
                a0=fmaf(wfbGE[32],q8.x,a0); a1=fmaf(wfbGE[33],q8.y,a1); a2=fmaf(wfbGE[34],q8.z,a2); a3=fmaf(wfbGE[35],q8.w,a3);
                float s = ((a0+a1)+(a2+a3)) + ((a4+a5)+(a6+a7));
                float e = fex2(s);
                float relv = rrp * frcp(1.0f + e);
                ip = ip_n; rrp = rrp_m - relv;
                if (l < NBC) relrow[tbase+i] = relv;
                /* ---- stage 4: rel shfl broadcast -> y matvecs ---- */
                float rl0 = __shfl_sync(0xffffffffu, relv, 0);
                float rl1 = __shfl_sync(0xffffffffu, relv, 1);
                float rl2 = __shfl_sync(0xffffffffu, relv, 2);
                float rl3 = __shfl_sync(0xffffffffu, relv, 3);
                float rl4 = __shfl_sync(0xffffffffu, relv, 4);
                float rl5 = __shfl_sync(0xffffffffu, relv, 5);
                float rl6 = __shfl_sync(0xffffffffu, relv, 6);
                float rl7 = __shfl_sync(0xffffffffu, relv, 7);
                float rl8 = __shfl_sync(0xffffffffu, relv, 8);
                float rl9 = __shfl_sync(0xffffffffu, relv, 9);
                float rl10 = __shfl_sync(0xffffffffu, relv, 10);
                float rl11 = __shfl_sync(0xffffffffu, relv, 11);
                float rl12 = __shfl_sync(0xffffffffu, relv, 12);
                float rl13 = __shfl_sync(0xffffffffu, relv, 13);
                float ya0,ya1,ya2,ya3, yg0,yg1,yg2,yg3, yh0,yh1,yh2,yh3;
                ya0 = wyA[0]*rl0;  ya1 = wyA[1]*rl1;  ya2 = wyA[2]*rl2;  ya3 = wyA[3]*rl3;
                yg0 = wyG[0]*rl0;  yg1 = wyG[1]*rl1;  yg2 = wyG[2]*rl2;  yg3 = wyG[3]*rl3;
                yh0 = wyH[0]*rl0;  yh1 = wyH[1]*rl1;  yh2 = wyH[2]*rl2;  yh3 = wyH[3]*rl3;
                ya0=fmaf(wyA[4],rl4,ya0); ya1=fmaf(wyA[5],rl5,ya1); ya2=fmaf(wyA[6],rl6,ya2); ya3=fmaf(wyA[7],rl7,ya3);
                yg0=fmaf(wyG[4],rl4,yg0); yg1=fmaf(wyG[5],rl5,yg1); yg2=fmaf(wyG[6],rl6,yg2); yg3=fmaf(wyG[7],rl7,yg3);
                yh0=fmaf(wyH[4],rl4,yh0); yh1=fmaf(wyH[5],rl5,yh1); yh2=fmaf(wyH[6],rl6,yh2); yh3=fmaf(wyH[7],rl7,yh3);
                ya0=fmaf(wyA[8],rl8,ya0); ya1=fmaf(wyA[9],rl9,ya1); ya2=fmaf(wyA[10],rl10,ya2); ya3=fmaf(wyA[11],rl11,ya3);
                yg0=fmaf(wyG[8],rl8,yg0); yg1=fmaf(wyG[9],rl9,yg1); yg2=fmaf(wyG[10],rl10,yg2); yg3=fmaf(wyG[11],rl11,yg3);
                yh0=fmaf(wyH[8],rl8,yh0); yh1=fmaf(wyH[9],rl9,yh1); yh2=fmaf(wyH[10],rl10,yh2); yh3=fmaf(wyH[11],rl11,yh3);
                ya0=fmaf(wyA[12],rl12,ya0); ya1=fmaf(wyA[13],rl13,ya1);
                yg0=fmaf(wyG[12],rl12,yg0); yg1=fmaf(wyG[13],rl13,yg1);
                yh0=fmaf(wyH[12],rl12,yh0); yh1=fmaf(wyH[13],rl13,yh1);
                float yA = (ya0+ya1)+(ya2+ya3);
                float yG = (yg0+yg1)+(yg2+yg3);
                float yH = (yh0+yh1)+(yh2+yh3);
                /* carried pre-activations: ONE fma after y */
                cvA   = fmaf(dkA, yA, bDA);
                baseG = fmaf(dkG, yG, bDG);
                baseH = fmaf(dkH, yH, bDH);
                if (l < NACL) ringA[l*53+ri] = yA;
                ringG[l*53+ri] = yG;
                if (l < 3) ringG[(l+32)*53+ri] = yH;
                A1 = fmaf(kA1, yA, bA1);
                A2 = fmaf(kA2, yA, bA2);
                G1 = fmaf(kG1, yG, bG1);
                G2 = fmaf(kG2, yG, bG2);
                H1 = fmaf(kH1, yH, bH1);
                H2 = fmaf(kH2, yH, bH2);
                ri = (ri == KACN-1) ? 0 : ri+1;
            }
            __syncwarp();
        }
    }
#undef LOADCHUNK
#undef STORECHUNK
}

// ---------------- iGluSnFR readout: 32-tap FIR over rel ----------------
__global__ void out_kernel(float* __restrict__ out){
    __shared__ float skg[K1];
    int tid = threadIdx.x;
    if (tid < K1) skg[tid] = g_kglu[tid];
    __syncthreads();
    int oid = blockIdx.x*blockDim.x + tid;
    if (oid >= 2*NBC*TN) return;
    int n  = oid & (TN-1);
    int pc = oid >> 15;
    const float* r = g_rel + pc*RELSTRIDE + n;
    float a0 = 0.f, a1 = 0.f;
    #pragma unroll
    for (int j = 0; j < K1; j++){
        float v = r[K1-1-j];
        if (j & 1) a1 = fmaf(skg[j], v, a1);
        else       a0 = fmaf(skg[j], v, a0);
    }
    out[oid] = a0 + a1;
}

extern "C" void kernel_launch(void* const* d_in, const int* in_sizes, int n_in,
                              void* d_out, int out_size){
    (void)in_sizes; (void)n_in; (void)out_size;
    const float* x  = (const float*)d_in[0];
    const float* sb = (const float*)d_in[1];
    const float* ss = (const float*)d_in[2];

    setup_kernel<<<1, 64>>>((const float*)d_in[3]);
    xp_kernel<<<(XPLEN+255)/256, 256>>>(x, sb, ss);
    drive_kernel<<<(NSTEPS+127)/128, 128>>>();
    scan_kernel<<<2, 32>>>(
        (const float*)d_in[4],  (const float*)d_in[5],
        (const float*)d_in[6],  (const float*)d_in[7],
        (const float*)d_in[8],  (const float*)d_in[9],
        (const float*)d_in[10], (const float*)d_in[11],
        (const float*)d_in[12], (const float*)d_in[13],
        (const float*)d_in[14], (const float*)d_in[15],
        (const float*)d_in[16], (const float*)d_in[17],
        (const float*)d_in[18], (const float*)d_in[19],
        (const float*)d_in[20], (const float*)d_in[21],
        (const float*)d_in[22], (const float*)d_in[23],
        (const float*)d_in[24], (const float*)d_in[25]);
    out_kernel<<<(2*NBC*TN+255)/256, 256>>>((float*)d_out);
}

// round 5
// speedup vs baseline: 1.0774x; 1.0774x over previous
#include <cuda_runtime.h>
#include <cstdint>

#define TN 32768
#define TLOOP 32799
#define NCHUNK 2050
#define NSTEPS (NCHUNK*16)   /* 32800 */
#define NBC 14
#define NACL 10
#define NACG 35
#define KACN 52
#define K0 20
#define K1 32
#define PADL 50              /* (K0-1)+(K1-1) */
#define XPLEN (TN + PADL)    /* 32818 */
#define RELSTRIDE 32832
#define FULLM 0xffffffffu

__device__ float g_xp[XPLEN];
__device__ float g_drive[NSTEPS*NBC];
__device__ float g_rel[2*NBC*RELSTRIDE];
__device__ float g_kbc[NBC*K0];
__device__ float g_kglu[K1];

__device__ __forceinline__ float ftanh(float x){
    float y; asm("tanh.approx.f32 %0, %1;" : "=f"(y) : "f"(x)); return y;
}
__device__ __forceinline__ float fex2(float x){
    float y; asm("ex2.approx.f32 %0, %1;" : "=f"(y) : "f"(x)); return y;
}
__device__ __forceinline__ float frcp(float x){
    float y; asm("rcp.approx.f32 %0, %1;" : "=f"(y) : "f"(x)); return y;
}
/* ---- packed fp32x2 ops (FFMA2 path, full fp32 precision) ---- */
__device__ __forceinline__ uint64_t pk(float lo, float hi){
    uint64_t r; asm("mov.b64 %0, {%1,%2};" : "=l"(r) : "f"(lo), "f"(hi)); return r;
}
__device__ __forceinline__ void upk(uint64_t v, float &lo, float &hi){
    asm("mov.b64 {%0,%1}, %2;" : "=f"(lo), "=f"(hi) : "l"(v));
}
__device__ __forceinline__ uint64_t fma2(uint64_t a, uint64_t b, uint64_t c){
    uint64_t d; asm("fma.rn.f32x2 %0, %1, %2, %3;" : "=l"(d) : "l"(a), "l"(b), "l"(c)); return d;
}
__device__ __forceinline__ uint64_t mul2(uint64_t a, uint64_t b){
    uint64_t d; asm("mul.rn.f32x2 %0, %1, %2;" : "=l"(d) : "l"(a), "l"(b)); return d;
}
__device__ __forceinline__ uint64_t ld64s(const float* p){
    return *reinterpret_cast<const uint64_t*>(p);
}

// double-exponential AC kernel -> IIR coefficients (exact FIR-equivalent with
// truncation correction): kern(L) = A*r1^L - B*r2^L (L=0 newest), L2-normalized
__device__ __forceinline__ void ac_coef(float ltr, float ltd,
    float &A, float &B, float &r1, float &r2, float &c1, float &c2){
    float tr = expf(ltr), td = expf(ltd);
    float beta = (td + tr) / (td * tr);
    float n2 = 0.f;
    for (int k = 0; k < KACN; k++){
        float t = 0.8f - (float)k * (1.0f/64.0f);
        float v = expf(-t/td) - expf(-beta*t);
        n2 = fmaf(v, v, n2);
    }
    float inv = 1.0f / sqrtf(n2);
    const float c0 = 0.8f - 51.0f*(1.0f/64.0f);
    A  = expf(-c0/td) * inv;
    B  = expf(-beta*c0) * inv;
    r1 = expf(-1.0f/(64.0f*td));
    r2 = expf(-beta*(1.0f/64.0f));
    c1 = expf(-0.8125f/td);        /* r1^52 */
    c2 = expf(-beta*0.8125f);      /* r2^52 */
}

// ---------------- setup: BC biphasic kernels + iGluSnFR kernel ----------------
__global__ void setup_kernel(const float* __restrict__ lks){
    int t = threadIdx.x;
    if (t < NBC){
        float speed = expf(lks[t]);
        float ct = (t < 5) ? -1.0f : 1.0f;
        float vals[K0]; float n2 = 0.f;
        #pragma unroll
        for (int j = 0; j < K0; j++){
            float ts = (float)j * (1.0f/64.0f) * speed;
            float a = ts / 0.05f, b = ts / 0.1f;
            float v = a*a*expf(-a) - 0.8f*b*b*expf(-b);
            v *= ct;
            vals[j] = v; n2 += v*v;
        }
        float inv = 1.0f / sqrtf(n2);
        #pragma unroll
        for (int j = 0; j < K0; j++) g_kbc[t*K0+j] = vals[j]*inv;
    }
    if (t == 32){
        float vals[K1]; float s = 0.f;
        #pragma unroll
        for (int j = 0; j < K1; j++){
            float tg = (float)j * (1.0f/64.0f);
            float v = (1.0f - expf(-tg/0.02f)) * expf(-tg/0.1f);
            vals[j] = v; s += v;
        }
        #pragma unroll
        for (int j = 0; j < K1; j++) g_kglu[j] = vals[j]/s;
    }
}

// ---------------- stimulus affine + edge padding ----------------
__global__ void xp_kernel(const float* __restrict__ x,
                          const float* __restrict__ sb,
                          const float* __restrict__ ss){
    int i = blockIdx.x*blockDim.x + threadIdx.x;
    if (i >= XPLEN) return;
    float es = expf(ss[0]); float b = sb[0];
    int s = i - PADL; if (s < 0) s = 0;
    g_xp[i] = x[s]*es + b;
}

// ---------------- per-BC 20-tap FIR -> drive[NSTEPS][NBC] ----------------
__global__ void drive_kernel(){
    __shared__ float skb[NBC*K0];
    int tid = threadIdx.x;
    for (int i = tid; i < NBC*K0; i += blockDim.x) skb[i] = g_kbc[i];
    __syncthreads();
    int n = blockIdx.x*blockDim.x + tid;
    if (n >= NSTEPS) return;
    if (n >= TLOOP){
        #pragma unroll
        for (int c = 0; c < NBC; c++) g_drive[n*NBC+c] = 0.f;
        return;
    }
    float xw[K0];
    #pragma unroll
    for (int j = 0; j < K0; j++) xw[j] = g_xp[n + j];
    #pragma unroll
    for (int c = 0; c < NBC; c++){
        float a0 = 0.f, a1 = 0.f;
        #pragma unroll
        for (int j = 0; j < K0; j++){
            float w = skb[c*K0+j];
            float v = xw[K0-1-j];
            if (j & 1) a1 = fmaf(w, v, a1); else a0 = fmaf(w, v, a0);
        }
        g_drive[n*NBC+c] = a0 + a1;
    }
}

// ---------------- the sequential scan: 2 blocks (pathways) x 1 warp ----------------
__global__ void __launch_bounds__(32,1) scan_kernel(
    const float* __restrict__ P_sigoff, const float* __restrict__ P_lslope,
    const float* __restrict__ P_lp01,  const float* __restrict__ P_lp12,
    const float* __restrict__ P_lipc,  const float* __restrict__ P_lrrpc,
    const float* __restrict__ P_ipst,  const float* __restrict__ P_rrpst,
    const float* __restrict__ P_laclbc, const float* __restrict__ P_lbcacl,
    const float* __restrict__ P_acltr, const float* __restrict__ P_acltd,
    const float* __restrict__ P_aclsl, const float* __restrict__ P_aclof,
    const float* __restrict__ P_lacgbc, const float* __restrict__ P_lbcacg,
    const float* __restrict__ P_acgtr, const float* __restrict__ P_acgtd,
    const float* __restrict__ P_acgsl, const float* __restrict__ P_acgof,
    const float* __restrict__ P_laclacg, const float* __restrict__ P_bcnoff)
{
    const int path = blockIdx.x;
    const int l = threadIdx.x;
    __shared__ float ringA[NACL*53];
    __shared__ float ringG[NACG*53];
    __shared__ float dbuf[2][16*NBC];
    __shared__ __align__(16) float sm_tvA[12];
    __shared__ __align__(16) float sm_tvG[40];
    __shared__ __align__(16) float sm_rel[16];
    for (int i = l; i < NACL*53; i += 32) ringA[i] = 0.f;
    for (int i = l; i < NACG*53; i += 32) ringG[i] = 0.f;
    if (l < 12) sm_tvA[l] = 0.f;
    { if (l < 40) sm_tvG[l] = 0.f; if (l+32 < 40) sm_tvG[l+32] = 0.f; }
    if (l < 16) sm_rel[l] = 0.f;

    const bool prim = (l < NBC);
    const int bc = prim ? l : ((l >= 16 && l < 16+NBC) ? (l-16) : -1);

    // ---- BC role: exp-form final sigmoid, log2e+slope pre-folded ----
    float cP=0.f, mBC=0.f, c_p01=0.f, c_p12=0.f, c_ipcap=0.f, c_irrp=0.f;
    float ip=0.f, rrp=0.f;
    float mh = 0.f;                               /* 0.5*mBC for this lane's BC cell */
    if (bc >= 0) mh = -0.5f*1.44269504f*expf(P_lslope[bc]);
    uint64_t wA2[5], wG2[10];
    #pragma unroll
    for (int k = 0; k < 5; k++) wA2[k] = 0;
    #pragma unroll
    for (int k = 0; k < 10; k++) wG2[k] = 0;
    if (prim){
        float off   = P_sigoff[l] + (path ? P_bcnoff[l] : 0.f);
        mBC = 2.0f*mh;
        c_p01   = expf(P_lp01[l]);
        c_p12   = expf(P_lp12[l]);
        c_ipcap = expf(P_lipc[l]);
        float rc = expf(P_lrrpc[l]);
        c_irrp = 1.0f / rc;
        ip  = c_ipcap / (1.0f + expf(-P_ipst[l]));
        rrp = rc      / (1.0f + expf(-P_rrpst[l]));
        float sA = 0.f, sG = 0.f;
        #pragma unroll
        for (int k = 0; k < 5; k++){
            float w0 = -expf(P_laclbc[l*NACL+2*k]);
            float w1 = -expf(P_laclbc[l*NACL+2*k+1]);
            sA += w0 + w1;
            wA2[k] = pk(mh*w0, mh*w1);
        }
        if (path){
            #pragma unroll
            for (int j = 0; j < NACG; j++) sG += -expf(P_lacgbc[l*NACG+j]);
            #pragma unroll
            for (int k = 0; k < 10; k++){       /* primary: taps 0..19 */
                float w0 = mh*(-expf(P_lacgbc[l*NACG+2*k]));
                float w1 = mh*(-expf(P_lacgbc[l*NACG+2*k+1]));
                wG2[k] = pk(w0, w1);
            }
        }
        cP = mBC*(0.5f*(sA+sG) - off);
    } else if (bc >= 0 && path){
        #pragma unroll
        for (int k = 0; k < 10; k++){           /* mirror: taps 20..39 (>=35 zero) */
            int j0 = 20+2*k, j1 = 21+2*k;
            float w0 = (j0 < NACG) ? mh*(-expf(P_lacgbc[bc*NACG+j0])) : 0.f;
            float w1 = (j1 < NACG) ? mh*(-expf(P_lacgbc[bc*NACG+j1])) : 0.f;
            wG2[k] = pk(w0, w1);
        }
    }

    // ---- ACL role (lane < 10): packed E-state ----
    uint64_t rA2p=0, nkAc2=0, kA12p=0, wyA2[7];
    float caA=0.f, dkA=0.f;
    #pragma unroll
    for (int k = 0; k < 7; k++) wyA2[k] = 0;
    if (l < NACL){
        float A,B,r1,r2,c1,c2;
        ac_coef(P_acltr[l], P_acltd[l], A,B,r1,r2,c1,c2);
        float ha = 0.5f*expf(P_aclsl[l]);
        float kA1 = ha*A, kA2 = ha*B;
        rA2p  = pk(r1, r2);
        nkAc2 = pk(-kA1*c1, -kA2*c2);
        kA12p = pk(kA1, kA2);
        caA = -ha*P_aclof[l];
        dkA = kA1 - kA2;
        #pragma unroll
        for (int k = 0; k < 7; k++)
            wyA2[k] = pk(expf(P_lbcacl[l*NBC+2*k]), expf(P_lbcacl[l*NBC+2*k+1]));
    }

    // ---- ACG roles (pathway 2 only): g = lane, h = lane+32 (lanes 0..2) ----
    uint64_t rG2p=0, nkGc2=0, kG12p=0, wGa2[5], wyG2[7];
    uint64_t rH2p=0, nkHc2=0, kH12p=0, wHa2[5], wyH2[7];
    float cgG=0.f, dkG=0.f, cgH=0.f, dkH=0.f;
    #pragma unroll
    for (int k = 0; k < 5; k++){ wGa2[k]=0; wHa2[k]=0; }
    #pragma unroll
    for (int k = 0; k < 7; k++){ wyG2[k]=0; wyH2[k]=0; }
    if (path){
        float A,B,r1,r2,c1,c2;
        ac_coef(P_acgtr[l], P_acgtd[l], A,B,r1,r2,c1,c2);
        float hg = 0.5f*expf(P_acgsl[l]);
        float kG1 = hg*A, kG2 = hg*B;
        rG2p  = pk(r1, r2);
        nkGc2 = pk(-kG1*c1, -kG2*c2);
        kG12p = pk(kG1, kG2);
        dkG = kG1 - kG2;
        float sw = 0.f;
        #pragma unroll
        for (int k = 0; k < 5; k++){
            float w0 = -expf(P_laclacg[l*NACL+2*k]);
            float w1 = -expf(P_laclacg[l*NACL+2*k+1]);
            sw += w0 + w1;
            wGa2[k] = pk(hg*0.5f*w0, hg*0.5f*w1);
        }
        cgG = hg*(0.5f*sw - P_acgof[l]);
        #pragma unroll
        for (int k = 0; k < 7; k++)
            wyG2[k] = pk(expf(P_lbcacg[l*NBC+2*k]), expf(P_lbcacg[l*NBC+2*k+1]));
        if (l < 3){
            int h = l + 32;
            ac_coef(P_acgtr[h], P_acgtd[h], A,B,r1,r2,c1,c2);
            float hh = 0.5f*expf(P_acgsl[h]);
            float kH1 = hh*A, kH2 = hh*B;
            rH2p  = pk(r1, r2);
            nkHc2 = pk(-kH1*c1, -kH2*c2);
            kH12p = pk(kH1, kH2);
            dkH = kH1 - kH2;
            float swh = 0.f;
            #pragma unroll
            for (int k = 0; k < 5; k++){
                float w0 = -expf(P_laclacg[h*NACL+2*k]);
                float w1 = -expf(P_laclacg[h*NACL+2*k+1]);
                swh += w0 + w1;
                wHa2[k] = pk(hh*0.5f*w0, hh*0.5f*w1);
            }
            cgH = hh*(0.5f*swh - P_acgof[h]);
            #pragma unroll
            for (int k = 0; k < 7; k++)
                wyH2[k] = pk(expf(P_lbcacg[h*NBC+2*k]), expf(P_lbcacg[h*NBC+2*k+1]));
        }
    }
    __syncwarp();

    float* relrow = g_rel + (path*NBC + (prim ? l : 0))*RELSTRIDE;
    uint64_t A12 = 0, G12 = 0, H12 = 0;
    float cvA = caA, baseG = cgG, baseH = cgH;
    int ri = 0;

    float fd0,fd1,fd2,fd3,fd4,fd5,fd6;
#define LOADCHUNK(k) do{ const float* _p = g_drive + (k)*224 + l; \
        fd0=_p[0]; fd1=_p[32]; fd2=_p[64]; fd3=_p[96]; fd4=_p[128]; fd5=_p[160]; fd6=_p[192]; }while(0)
#define STORECHUNK(bi) do{ float* _q = dbuf[bi] + l; \
        _q[0]=fd0; _q[32]=fd1; _q[64]=fd2; _q[96]=fd3; _q[128]=fd4; _q[160]=fd5; _q[192]=fd6; }while(0)

    LOADCHUNK(0); STORECHUNK(0); LOADCHUNK(1);
    __syncwarp();

    if (path == 0){
        // ---------- LNR pathway: ACL feedback only (packed) ----------
        for (int c = 0; c < NCHUNK; c++){
            int cur = c & 1;
            STORECHUNK(cur^1);
            int nk = (c+2 < NCHUNK) ? (c+2) : (NCHUNK-1);
            LOADCHUNK(nk);
            __syncwarp();
            const float* db = dbuf[cur];
            int tbase = c*16;
            #pragma unroll 4
            for (int i = 0; i < 16; i++){
                /* off-chain */
                float yoA = (l < NACL) ? ringA[l*53+ri] : 0.f;
                float xi  = prim ? db[i*NBC + l] : 0.f;
                float fbBase = fmaf(mBC, xi, cP);
                float t12 = c_p12*ip*(1.0f - rrp*c_irrp);
                float ip_n = ip + c_p01*(c_ipcap - ip) - t12;
                float rrp_m = rrp + t12;
                uint64_t pbA = fma2(nkAc2, pk(yoA,yoA), mul2(rA2p, A12));
                float bA1, bA2; upk(pbA, bA1, bA2);
                float bDA = (bA1 - bA2) + caA;
                /* stage1: tanh + smem broadcast */
                float tvA = ftanh(cvA);
                if (l < NACL) sm_tvA[l] = tvA;
                __syncwarp();
                uint64_t tp0 = ld64s(sm_tvA+0), tp1 = ld64s(sm_tvA+2),
                         tp2 = ld64s(sm_tvA+4), tp3 = ld64s(sm_tvA+6),
                         tp4 = ld64s(sm_tvA+8);
                /* fb: 5 packed fmas */
                uint64_t f0 = pk(fbBase, 0.f);
                uint64_t f1 = mul2(wA2[1], tp1);
                f0 = fma2(wA2[0], tp0, f0);
                f1 = fma2(wA2[2], tp2, f1);
                f0 = fma2(wA2[3], tp3, f0);
                f1 = fma2(wA2[4], tp4, f1);
                float a0,a1,a2,a3; upk(f0,a0,a1); upk(f1,a2,a3);
                float e = fex2((a0+a1)+(a2+a3));
                float relv = rrp * frcp(1.0f + e);
                ip = ip_n; rrp = rrp_m - relv;
                if (prim){ relrow[tbase+i] = relv; sm_rel[l] = relv; }
                __syncwarp();
                /* yA: 7 packed fmas */
                uint64_t rp0 = ld64s(sm_rel+0), rp1 = ld64s(sm_rel+2),
                         rp2 = ld64s(sm_rel+4), rp3 = ld64s(sm_rel+6),
                         rp4 = ld64s(sm_rel+8), rp5 = ld64s(sm_rel+10),
                         rp6 = ld64s(sm_rel+12);
                uint64_t yacc0 = mul2(wyA2[0], rp0);
                uint64_t yacc1 = mul2(wyA2[1], rp1);
                yacc0 = fma2(wyA2[2], rp2, yacc0);
                yacc1 = fma2(wyA2[3], rp3, yacc1);
                yacc0 = fma2(wyA2[4], rp4, yacc0);
                yacc1 = fma2(wyA2[5], rp5, yacc1);
                yacc0 = fma2(wyA2[6], rp6, yacc0);
                float y0,y1,y2,y3; upk(yacc0,y0,y1); upk(yacc1,y2,y3);
                float yA = (y0+y1)+(y2+y3);
                cvA = fmaf(dkA, yA, bDA);
                if (l < NACL) ringA[l*53+ri] = yA;
                A12 = fma2(kA12p, pk(yA,yA), pbA);
                ri = (ri == KACN-1) ? 0 : ri+1;
            }
            __syncwarp();
        }
    } else {
        // ---------- BCN pathway: ACL + ACG feedback (packed + mirror split) ----------
        const float* gq = sm_tvG + ((l & 16) ? 20 : 0);   /* per-half tvG base */
        for (int c = 0; c < NCHUNK; c++){
            int cur = c & 1;
            STORECHUNK(cur^1);
            int nk = (c+2 < NCHUNK) ? (c+2) : (NCHUNK-1);
            LOADCHUNK(nk);
            __syncwarp();
            const float* db = dbuf[cur];
            int tbase = c*16;
            #pragma unroll 2
            for (int i = 0; i < 16; i++){
                /* ---- off-chain top work ---- */
                float yoA = (l < NACL) ? ringA[l*53+ri] : 0.f;
                float yoG = ringG[l*53+ri];
                float yoH = (l < 3) ? ringG[(l+32)*53+ri] : 0.f;
                float xi  = prim ? db[i*NBC + l] : 0.f;
                float fbBase = fmaf(mBC, xi, cP);
                float t12 = c_p12*ip*(1.0f - rrp*c_irrp);
                float ip_n = ip + c_p01*(c_ipcap - ip) - t12;
                float rrp_m = rrp + t12;
                uint64_t pbA = fma2(nkAc2, pk(yoA,yoA), mul2(rA2p, A12));
                uint64_t pbG = fma2(nkGc2, pk(yoG,yoG), mul2(rG2p, G12));
                uint64_t pbH = fma2(nkHc2, pk(yoH,yoH), mul2(rH2p, H12));
                float bA1,bA2; upk(pbA,bA1,bA2); float bDA = (bA1-bA2)+caA;
                float bG1,bG2; upk(pbG,bG1,bG2); float bDG = (bG1-bG2)+cgG;
                float bH1,bH2; upk(pbH,bH1,bH2); float bDH = (bH1-bH2)+cgH;
                /* ---- stage 1: ACL tanh + smem broadcast ---- */
                float tvA = ftanh(cvA);
                if (l < NACL) sm_tvA[l] = tvA;
                __syncwarp();
                uint64_t tp0 = ld64s(sm_tvA+0), tp1 = ld64s(sm_tvA+2),
                         tp2 = ld64s(sm_tvA+4), tp3 = ld64s(sm_tvA+6),
                         tp4 = ld64s(sm_tvA+8);
                /* ---- stage 2: ACG pre-activations (packed) ---- */
                uint64_t pg = pk(baseG, 0.f);
                uint64_t ph = pk(baseH, 0.f);
                uint64_t ae = mul2(wA2[0], tp0);
                pg = fma2(wGa2[0], tp0, pg);  ph = fma2(wHa2[0], tp0, ph);
                pg = fma2(wGa2[1], tp1, pg);  ph = fma2(wHa2[1], tp1, ph);
                ae = fma2(wA2[1], tp1, ae);
                pg = fma2(wGa2[2], tp2, pg);  ph = fma2(wHa2[2], tp2, ph);
                ae = fma2(wA2[2], tp2, ae);
                pg = fma2(wGa2[3], tp3, pg);  ph = fma2(wHa2[3], tp3, ph);
                ae = fma2(wA2[3], tp3, ae);
                pg = fma2(wGa2[4], tp4, pg);  ph = fma2(wHa2[4], tp4, ph);
                ae = fma2(wA2[4], tp4, ae);
                float pgl,pgh; upk(pg,pgl,pgh);
                float phl,phh; upk(ph,phl,phh);
                float tvG = ftanh(pgl + pgh);
                float tvH = ftanh(phl + phh);
                sm_tvG[l] = tvG;
                if (l < 3) sm_tvG[32+l] = tvH;
                __syncwarp();
                /* ---- stage 3: BC pre-activation, half-lane split, packed ----
                   primary lanes (0-13) taps 0-19; mirror lanes (16-29) taps 20-35 */
                uint64_t q0 = ld64s(gq+0),  q1 = ld64s(gq+2),  q2 = ld64s(gq+4),
                         q3 = ld64s(gq+6),  q4 = ld64s(gq+8),  q5 = ld64s(gq+10),
                         q6 = ld64s(gq+12), q7 = ld64s(gq+14), q8 = ld64s(gq+16),
                         q9 = ld64s(gq+18);
                uint64_t s0 = pk(fbBase, 0.f);
                uint64_t s1 = ae;
                uint64_t s2 = mul2(wG2[2], q2);
                s0 = fma2(wG2[0], q0, s0);
                s1 = fma2(wG2[1], q1, s1);
                s0 = fma2(wG2[3], q3, s0);
                s1 = fma2(wG2[4], q4, s1);
                s2 = fma2(wG2[5], q5, s2);
                s0 = fma2(wG2[6], q6, s0);
                s1 = fma2(wG2[7], q7, s1);
                s2 = fma2(wG2[8], q8, s2);
                s0 = fma2(wG2[9], q9, s0);
                float u0,u1,u2,u3,u4,u5;
                upk(s0,u0,u1); upk(s1,u2,u3); upk(s2,u4,u5);
                float s_loc = ((u0+u1)+(u2+u3))+(u4+u5);
                float s_oth = __shfl_down_sync(FULLM, s_loc, 16);
                float s = s_loc + s_oth;
                float e = fex2(s);
                float relv = rrp * frcp(1.0f + e);
                ip = ip_n; rrp = rrp_m - relv;
                if (prim){ relrow[tbase+i] = relv; sm_rel[l] = relv; }
                __syncwarp();
                /* ---- stage 4: packed y matvecs ---- */
                uint64_t rp0 = ld64s(sm_rel+0), rp1 = ld64s(sm_rel+2),
                         rp2 = ld64s(sm_rel+4), rp3 = ld64s(sm_rel+6),
                         rp4 = ld64s(sm_rel+8), rp5 = ld64s(sm_rel+10),
                         rp6 = ld64s(sm_rel+12);
                uint64_t aA = mul2(wyA2[0], rp0);
                uint64_t aG = mul2(wyG2[0], rp0);
                uint64_t aH = mul2(wyH2[0], rp0);
                aA = fma2(wyA2[1], rp1, aA); aG = fma2(wyG2[1], rp1, aG); aH = fma2(wyH2[1], rp1, aH);
                aA = fma2(wyA2[2], rp2, aA); aG = fma2(wyG2[2], rp2, aG); aH = fma2(wyH2[2], rp2, aH);
                aA = fma2(wyA2[3], rp3, aA); aG = fma2(wyG2[3], rp3, aG); aH = fma2(wyH2[3], rp3, aH);
                aA = fma2(wyA2[4], rp4, aA); aG = fma2(wyG2[4], rp4, aG); aH = fma2(wyH2[4], rp4, aH);
                aA = fma2(wyA2[5], rp5, aA); aG = fma2(wyG2[5], rp5, aG); aH = fma2(wyH2[5], rp5, aH);
                aA = fma2(wyA2[6], rp6, aA); aG = fma2(wyG2[6], rp6, aG); aH = fma2(wyH2[6], rp6, aH);
                float v0,v1; upk(aA,v0,v1); float yA = v0+v1;
                float w0,w1; upk(aG,w0,w1); float yG = w0+w1;
                float x0,x1; upk(aH,x0,x1); float yH = x0+x1;
                cvA   = fmaf(dkA, yA, bDA);
                baseG = fmaf(dkG, yG, bDG);
                baseH = fmaf(dkH, yH, bDH);
                if (l < NACL) ringA[l*53+ri] = yA;
                ringG[l*53+ri] = yG;
                if (l < 3) ringG[(l+32)*53+ri] = yH;
                A12 = fma2(kA12p, pk(yA,yA), pbA);
                G12 = fma2(kG12p, pk(yG,yG), pbG);
                H12 = fma2(kH12p, pk(yH,yH), pbH);
                ri = (ri == KACN-1) ? 0 : ri+1;
            }
            __syncwarp();
        }
    }
#undef LOADCHUNK
#undef STORECHUNK
}

// ---------------- iGluSnFR readout: 32-tap FIR over rel ----------------
__global__ void out_kernel(float* __restrict__ out){
    __shared__ float skg[K1];
    int tid = threadIdx.x;
    if (tid < K1) skg[tid] = g_kglu[tid];
    __syncthreads();
    int oid = blockIdx.x*blockDim.x + tid;
    if (oid >= 2*NBC*TN) return;
    int n  = oid & (TN-1);
    int pc = oid >> 15;
    const float* r = g_rel + pc*RELSTRIDE + n;
    float a0 = 0.f, a1 = 0.f;
    #pragma unroll
    for (int j = 0; j < K1; j++){
        float v = r[K1-1-j];
        if (j & 1) a1 = fmaf(skg[j], v, a1);
        else       a0 = fmaf(skg[j], v, a0);
    }
    out[oid] = a0 + a1;
}

extern "C" void kernel_launch(void* const* d_in, const int* in_sizes, int n_in,
                              void* d_out, int out_size){
    (void)in_sizes; (void)n_in; (void)out_size;
    const float* x  = (const float*)d_in[0];
    const float* sb = (const float*)d_in[1];
    const float* ss = (const float*)d_in[2];

    setup_kernel<<<1, 64>>>((const float*)d_in[3]);
    xp_kernel<<<(XPLEN+255)/256, 256>>>(x, sb, ss);
    drive_kernel<<<(NSTEPS+127)/128, 128>>>();
    scan_kernel<<<2, 32>>>(
        (const float*)d_in[4],  (const float*)d_in[5],
        (const float*)d_in[6],  (const float*)d_in[7],
        (const float*)d_in[8],  (const float*)d_in[9],
        (const float*)d_in[10], (const float*)d_in[11],
        (const float*)d_in[12], (const float*)d_in[13],
        (const float*)d_in[14], (const float*)d_in[15],
        (const float*)d_in[16], (const float*)d_in[17],
        (const float*)d_in[18], (const float*)d_in[19],
        (const float*)d_in[20], (const float*)d_in[21],
        (const float*)d_in[22], (const float*)d_in[23],
        (const float*)d_in[24], (const float*)d_in[25]);
    out_kernel<<<(2*NBC*TN+255)/256, 256>>>((float*)d_out);
}

// round 7
// speedup vs baseline: 1.6802x; 1.5594x over previous
#include <cuda_runtime.h>
#include <cstdint>

#define TN 32768
#define TLOOP 32799
#define NCHUNK 2050
#define NSTEPS (NCHUNK*16)   /* 32800 */
#define NBC 14
#define NACL 10
#define NACG 35
#define KACN 52
#define K0 20
#define K1 32
#define PADL 50              /* (K0-1)+(K1-1) */
#define XPLEN (TN + PADL)    /* 32818 */
#define RELSTRIDE 32832
#define FULLM 0xffffffffu

__device__ float g_xp[XPLEN];
__device__ float g_drive[NSTEPS*NBC];
__device__ float g_rel[2*NBC*RELSTRIDE];
__device__ float g_kbc[NBC*K0];
__device__ float g_kglu[K1];

__device__ __forceinline__ float ftanh(float x){
    float y; asm("tanh.approx.f32 %0, %1;" : "=f"(y) : "f"(x)); return y;
}
__device__ __forceinline__ float fex2(float x){
    float y; asm("ex2.approx.f32 %0, %1;" : "=f"(y) : "f"(x)); return y;
}
__device__ __forceinline__ float frcp(float x){
    float y; asm("rcp.approx.f32 %0, %1;" : "=f"(y) : "f"(x)); return y;
}
/* ---- packed fp32x2 ops (FFMA2 path, full fp32 precision) ---- */
__device__ __forceinline__ uint64_t pk(float lo, float hi){
    uint64_t r; asm("mov.b64 %0, {%1,%2};" : "=l"(r) : "f"(lo), "f"(hi)); return r;
}
__device__ __forceinline__ void upk(uint64_t v, float &lo, float &hi){
    asm("mov.b64 {%0,%1}, %2;" : "=f"(lo), "=f"(hi) : "l"(v));
}
__device__ __forceinline__ uint64_t fma2(uint64_t a, uint64_t b, uint64_t c){
    uint64_t d; asm("fma.rn.f32x2 %0, %1, %2, %3;" : "=l"(d) : "l"(a), "l"(b), "l"(c)); return d;
}
__device__ __forceinline__ uint64_t mul2(uint64_t a, uint64_t b){
    uint64_t d; asm("mul.rn.f32x2 %0, %1, %2;" : "=l"(d) : "l"(a), "l"(b)); return d;
}
__device__ __forceinline__ uint64_t ld64s(const float* p){
    return *reinterpret_cast<const uint64_t*>(p);
}

// double-exponential AC kernel -> IIR coefficients (exact FIR-equivalent with
// truncation correction): kern(L) = A*r1^L - B*r2^L (L=0 newest), L2-normalized
__device__ __forceinline__ void ac_coef(float ltr, float ltd,
    float &A, float &B, float &r1, float &r2, float &c1, float &c2){
    float tr = expf(ltr), td = expf(ltd);
    float beta = (td + tr) / (td * tr);
    float n2 = 0.f;
    for (int k = 0; k < KACN; k++){
        float t = 0.8f - (float)k * (1.0f/64.0f);
        float v = expf(-t/td) - expf(-beta*t);
        n2 = fmaf(v, v, n2);
    }
    float inv = 1.0f / sqrtf(n2);
    const float c0 = 0.8f - 51.0f*(1.0f/64.0f);
    A  = expf(-c0/td) * inv;
    B  = expf(-beta*c0) * inv;
    r1 = expf(-1.0f/(64.0f*td));
    r2 = expf(-beta*(1.0f/64.0f));
    c1 = expf(-0.8125f/td);        /* r1^52 */
    c2 = expf(-beta*0.8125f);      /* r2^52 */
}

// ---------------- setup: BC biphasic kernels + iGluSnFR kernel ----------------
__global__ void setup_kernel(const float* __restrict__ lks){
    int t = threadIdx.x;
    if (t < NBC){
        float speed = expf(lks[t]);
        float ct = (t < 5) ? -1.0f : 1.0f;
        float vals[K0]; float n2 = 0.f;
        #pragma unroll
        for (int j = 0; j < K0; j++){
            float ts = (float)j * (1.0f/64.0f) * speed;
            float a = ts / 0.05f, b = ts / 0.1f;
            float v = a*a*expf(-a) - 0.8f*b*b*expf(-b);
            v *= ct;
            vals[j] = v; n2 += v*v;
        }
        float inv = 1.0f / sqrtf(n2);
        #pragma unroll
        for (int j = 0; j < K0; j++) g_kbc[t*K0+j] = vals[j]*inv;
    }
    if (t == 32){
        float vals[K1]; float s = 0.f;
        #pragma unroll
        for (int j = 0; j < K1; j++){
            float tg = (float)j * (1.0f/64.0f);
            float v = (1.0f - expf(-tg/0.02f)) * expf(-tg/0.1f);
            vals[j] = v; s += v;
        }
        #pragma unroll
        for (int j = 0; j < K1; j++) g_kglu[j] = vals[j]/s;
    }
}

// ---------------- stimulus affine + edge padding ----------------
__global__ void xp_kernel(const float* __restrict__ x,
                          const float* __restrict__ sb,
                          const float* __restrict__ ss){
    int i = blockIdx.x*blockDim.x + threadIdx.x;
    if (i >= XPLEN) return;
    float es = expf(ss[0]); float b = sb[0];
    int s = i - PADL; if (s < 0) s = 0;
    g_xp[i] = x[s]*es + b;
}

// ---------------- per-BC 20-tap FIR -> drive[NSTEPS][NBC] ----------------
__global__ void drive_kernel(){
    __shared__ float skb[NBC*K0];
    int tid = threadIdx.x;
    for (int i = tid; i < NBC*K0; i += blockDim.x) skb[i] = g_kbc[i];
    __syncthreads();
    int n = blockIdx.x*blockDim.x + tid;
    if (n >= NSTEPS) return;
    if (n >= TLOOP){
        #pragma unroll
        for (int c = 0; c < NBC; c++) g_drive[n*NBC+c] = 0.f;
        return;
    }
    float xw[K0];
    #pragma unroll
    for (int j = 0; j < K0; j++) xw[j] = g_xp[n + j];
    #pragma unroll
    for (int c = 0; c < NBC; c++){
        float a0 = 0.f, a1 = 0.f;
        #pragma unroll
        for (int j = 0; j < K0; j++){
            float w = skb[c*K0+j];
            float v = xw[K0-1-j];
            if (j & 1) a1 = fmaf(w, v, a1); else a0 = fmaf(w, v, a0);
        }
        g_drive[n*NBC+c] = a0 + a1;
    }
}

// ---------------- the sequential scan: 2 blocks (pathways) x 1 warp ----------------
__global__ void __launch_bounds__(32,1) scan_kernel(
    const float* __restrict__ P_sigoff, const float* __restrict__ P_lslope,
    const float* __restrict__ P_lp01,  const float* __restrict__ P_lp12,
    const float* __restrict__ P_lipc,  const float* __restrict__ P_lrrpc,
    const float* __restrict__ P_ipst,  const float* __restrict__ P_rrpst,
    const float* __restrict__ P_laclbc, const float* __restrict__ P_lbcacl,
    const float* __restrict__ P_acltr, const float* __restrict__ P_acltd,
    const float* __restrict__ P_aclsl, const float* __restrict__ P_aclof,
    const float* __restrict__ P_lacgbc, const float* __restrict__ P_lbcacg,
    const float* __restrict__ P_acgtr, const float* __restrict__ P_acgtd,
    const float* __restrict__ P_acgsl, const float* __restrict__ P_acgof,
    const float* __restrict__ P_laclacg, const float* __restrict__ P_bcnoff)
{
    const int path = blockIdx.x;
    const int l = threadIdx.x;
    __shared__ float ringA[11*53];          /* rows 0-9 ACL, row 10 dummy */
    __shared__ float ringG[NACG*53];
    __shared__ float dbuf[2][16*NBC];
    __shared__ __align__(16) float sm_B[48];   /* [0..34] tvG/tvH, [35]=0, [36..45] tvA, [46..47] dummy */
    __shared__ __align__(16) float sm_tvA[12]; /* LNR only */
    __shared__ __align__(16) float sm_rel[16];
    for (int i = l; i < 11*53; i += 32) ringA[i] = 0.f;
    for (int i = l; i < NACG*53; i += 32) ringG[i] = 0.f;
    { if (l < 48) sm_B[l] = 0.f; if (l+32 < 48) sm_B[l+32] = 0.f; }
    if (l < 12) sm_tvA[l] = 0.f;
    if (l < 16) sm_rel[l] = 0.f;

    const bool prim = (l < NBC);
    const int bc = prim ? l : ((l >= 16 && l < 16+NBC) ? (l-16) : -1);

    // ---- BC pool role (prim lanes, both paths) ----
    float cP=0.f, mBC=0.f, c_p01=0.f, c_p12=0.f, c_ipcap=0.f, c_irrp=0.f;
    float ip=0.f, rrp=0.f;
    float mh = 0.f;
    if (bc >= 0) mh = -0.5f*1.44269504f*expf(P_lslope[bc]);
    if (prim){
        float off   = P_sigoff[l] + (path ? P_bcnoff[l] : 0.f);
        mBC = 2.0f*mh;
        c_p01   = expf(P_lp01[l]);
        c_p12   = expf(P_lp12[l]);
        c_ipcap = expf(P_lipc[l]);
        float rc = expf(P_lrrpc[l]);
        c_irrp = 1.0f / rc;
        ip  = c_ipcap / (1.0f + expf(-P_ipst[l]));
        rrp = rc      / (1.0f + expf(-P_rrpst[l]));
        float sA = 0.f, sG = 0.f;
        #pragma unroll
        for (int j = 0; j < NACL; j++) sA += -expf(P_laclbc[l*NACL+j]);
        if (path){
            #pragma unroll
            for (int j = 0; j < NACG; j++) sG += -expf(P_lacgbc[l*NACG+j]);
        }
        cP = mBC*(0.5f*(sA+sG) - off);
    }

    float* relrow = g_rel + (path*NBC + (prim ? l : 0))*RELSTRIDE;
    int ri = 0;

    float fd0,fd1,fd2,fd3,fd4,fd5,fd6;
#define LOADCHUNK(k) do{ const float* _p = g_drive + (k)*224 + l; \
        fd0=_p[0]; fd1=_p[32]; fd2=_p[64]; fd3=_p[96]; fd4=_p[128]; fd5=_p[160]; fd6=_p[192]; }while(0)
#define STORECHUNK(bi) do{ float* _q = dbuf[bi] + l; \
        _q[0]=fd0; _q[32]=fd1; _q[64]=fd2; _q[96]=fd3; _q[128]=fd4; _q[160]=fd5; _q[192]=fd6; }while(0)

    if (path == 0){
        // ================= LNR pathway (as R5) =================
        uint64_t wA2[5];
        #pragma unroll
        for (int k = 0; k < 5; k++) wA2[k] = 0;
        if (prim){
            #pragma unroll
            for (int k = 0; k < 5; k++){
                float w0 = -expf(P_laclbc[l*NACL+2*k]);
                float w1 = -expf(P_laclbc[l*NACL+2*k+1]);
                wA2[k] = pk(mh*w0, mh*w1);
            }
        }
        uint64_t rA2p=0, nkAc2=0, kA12p=0, wyA2[7];
        float caA=0.f, dkA=0.f;
        #pragma unroll
        for (int k = 0; k < 7; k++) wyA2[k] = 0;
        if (l < NACL){
            float A,B,r1,r2,c1,c2;
            ac_coef(P_acltr[l], P_acltd[l], A,B,r1,r2,c1,c2);
            float ha = 0.5f*expf(P_aclsl[l]);
            float kA1 = ha*A, kA2 = ha*B;
            rA2p  = pk(r1, r2);
            nkAc2 = pk(-kA1*c1, -kA2*c2);
            kA12p = pk(kA1, kA2);
            caA = -ha*P_aclof[l];
            dkA = kA1 - kA2;
            #pragma unroll
            for (int k = 0; k < 7; k++)
                wyA2[k] = pk(expf(P_lbcacl[l*NBC+2*k]), expf(P_lbcacl[l*NBC+2*k+1]));
        }
        __syncwarp();
        uint64_t A12 = 0;
        float cvA = caA;
        LOADCHUNK(0); STORECHUNK(0); LOADCHUNK(1);
        __syncwarp();
        for (int c = 0; c < NCHUNK; c++){
            int cur = c & 1;
            STORECHUNK(cur^1);
            int nk = (c+2 < NCHUNK) ? (c+2) : (NCHUNK-1);
            LOADCHUNK(nk);
            __syncwarp();
            const float* db = dbuf[cur];
            int tbase = c*16;
            #pragma unroll 4
            for (int i = 0; i < 16; i++){
                float yoA = (l < NACL) ? ringA[l*53+ri] : 0.f;
                float xi  = prim ? db[i*NBC + l] : 0.f;
                float fbBase = fmaf(mBC, xi, cP);
                float t12 = c_p12*ip*(1.0f - rrp*c_irrp);
                float ip_n = ip + c_p01*(c_ipcap - ip) - t12;
                float rrp_m = rrp + t12;
                uint64_t pbA = fma2(nkAc2, pk(yoA,yoA), mul2(rA2p, A12));
                float bA1, bA2; upk(pbA, bA1, bA2);
                float bDA = (bA1 - bA2) + caA;
                float tvA = ftanh(cvA);
                if (l < NACL) sm_tvA[l] = tvA;
                __syncwarp();
                uint64_t tp0 = ld64s(sm_tvA+0), tp1 = ld64s(sm_tvA+2),
                         tp2 = ld64s(sm_tvA+4), tp3 = ld64s(sm_tvA+6),
                         tp4 = ld64s(sm_tvA+8);
                uint64_t f0 = pk(fbBase, 0.f);
                uint64_t f1 = mul2(wA2[1], tp1);
                f0 = fma2(wA2[0], tp0, f0);
                f1 = fma2(wA2[2], tp2, f1);
                f0 = fma2(wA2[3], tp3, f0);
                f1 = fma2(wA2[4], tp4, f1);
                float a0,a1,a2,a3; upk(f0,a0,a1); upk(f1,a2,a3);
                float e = fex2((a0+a1)+(a2+a3));
                float relv = rrp * frcp(1.0f + e);
                ip = ip_n; rrp = rrp_m - relv;
                if (prim){ relrow[tbase+i] = relv; sm_rel[l] = relv; }
                __syncwarp();
                uint64_t rp0 = ld64s(sm_rel+0), rp1 = ld64s(sm_rel+2),
                         rp2 = ld64s(sm_rel+4), rp3 = ld64s(sm_rel+6),
                         rp4 = ld64s(sm_rel+8), rp5 = ld64s(sm_rel+10),
                         rp6 = ld64s(sm_rel+12);
                uint64_t y0 = mul2(wyA2[0], rp0);
                uint64_t y1 = mul2(wyA2[1], rp1);
                y0 = fma2(wyA2[2], rp2, y0);
                y1 = fma2(wyA2[3], rp3, y1);
                y0 = fma2(wyA2[4], rp4, y0);
                y1 = fma2(wyA2[5], rp5, y1);
                y0 = fma2(wyA2[6], rp6, y0);
                float v0,v1,v2,v3; upk(y0,v0,v1); upk(y1,v2,v3);
                float yA = (v0+v1)+(v2+v3);
                cvA = fmaf(dkA, yA, bDA);
                if (l < NACL) ringA[l*53+ri] = yA;
                A12 = fma2(kA12p, pk(yA,yA), pbA);
                ri = (ri == KACN-1) ? 0 : ri+1;
            }
            __syncwarp();
        }
    } else {
        // ================= BCN pathway: role-redistributed =================
        const bool isA = (l >= 16 && l < 26);
        const bool isH = (l < 3);
        // ---- G channel (every lane owns ACG channel l) ----
        uint64_t rG2p, nkGc2, kG12p, wGa2[5], wyG2[7];
        float cgG, dkG;
        {
            float A,B,r1,r2,c1,c2;
            ac_coef(P_acgtr[l], P_acgtd[l], A,B,r1,r2,c1,c2);
            float hg = 0.5f*expf(P_acgsl[l]);
            float k1 = hg*A, k2 = hg*B;
            rG2p  = pk(r1, r2);
            nkGc2 = pk(-k1*c1, -k2*c2);
            kG12p = pk(k1, k2);
            dkG = k1 - k2;
            float sw = 0.f;
            #pragma unroll
            for (int k = 0; k < 5; k++){
                float w0 = -expf(P_laclacg[l*NACL+2*k]);
                float w1 = -expf(P_laclacg[l*NACL+2*k+1]);
                sw += w0 + w1;
                wGa2[k] = pk(hg*0.5f*w0, hg*0.5f*w1);
            }
            cgG = hg*(0.5f*sw - P_acgof[l]);
            #pragma unroll
            for (int k = 0; k < 7; k++)
                wyG2[k] = pk(expf(P_lbcacg[l*NBC+2*k]), expf(P_lbcacg[l*NBC+2*k+1]));
        }
        // ---- Sec channel: A on lanes 16-25, H(=ACG 32-34) on lanes 0-2 ----
        uint64_t rS2p=0, nkSc2=0, kS12p=0, wyS2[7], wHa2[5];
        float cS=0.f, dkS=0.f;
        float* secPtr = ringA + 10*53;
        #pragma unroll
        for (int k = 0; k < 7; k++) wyS2[k] = 0;
        #pragma unroll
        for (int k = 0; k < 5; k++) wHa2[k] = 0;
        if (isA){
            int a = l - 16;
            float A,B,r1,r2,c1,c2;
            ac_coef(P_acltr[a], P_acltd[a], A,B,r1,r2,c1,c2);
            float ha = 0.5f*expf(P_aclsl[a]);
            float k1 = ha*A, k2 = ha*B;
            rS2p = pk(r1,r2); nkSc2 = pk(-k1*c1,-k2*c2); kS12p = pk(k1,k2);
            dkS = k1 - k2;
            cS = -ha*P_aclof[a];
            #pragma unroll
            for (int k = 0; k < 7; k++)
                wyS2[k] = pk(expf(P_lbcacl[a*NBC+2*k]), expf(P_lbcacl[a*NBC+2*k+1]));
            secPtr = ringA + a*53;
        } else if (isH){
            int h = l + 32;
            float A,B,r1,r2,c1,c2;
            ac_coef(P_acgtr[h], P_acgtd[h], A,B,r1,r2,c1,c2);
            float hh = 0.5f*expf(P_acgsl[h]);
            float k1 = hh*A, k2 = hh*B;
            rS2p = pk(r1,r2); nkSc2 = pk(-k1*c1,-k2*c2); kS12p = pk(k1,k2);
            dkS = k1 - k2;
            float swh = 0.f;
            #pragma unroll
            for (int k = 0; k < 5; k++){
                float w0 = -expf(P_laclacg[h*NACL+2*k]);
                float w1 = -expf(P_laclacg[h*NACL+2*k+1]);
                swh += w0 + w1;
                wHa2[k] = pk(hh*0.5f*w0, hh*0.5f*w1);
            }
            cS = hh*(0.5f*swh - P_acgof[h]);
            #pragma unroll
            for (int k = 0; k < 7; k++)
                wyS2[k] = pk(expf(P_lbcacg[h*NBC+2*k]), expf(P_lbcacg[h*NBC+2*k+1]));
            secPtr = ringG + h*53;
        }
        const int secSlot = isA ? (36 + (l-16)) : 46;
        const int hSlot   = isH ? (32 + l) : 46;
        // ---- BC feedback weights: primary taps 0-19; mirror taps 20-45 (35=0, 36-45=ACL) ----
        uint64_t wFB[13];
        #pragma unroll
        for (int k = 0; k < 13; k++) wFB[k] = 0;
        if (prim){
            #pragma unroll
            for (int k = 0; k < 10; k++){
                float w0 = mh*(-expf(P_lacgbc[l*NACG+2*k]));
                float w1 = mh*(-expf(P_lacgbc[l*NACG+2*k+1]));
                wFB[k] = pk(w0, w1);
            }
        } else if (bc >= 0){
            #pragma unroll
            for (int k = 0; k < 13; k++){
                int j0 = 20+2*k, j1 = 21+2*k;
                float w0 = (j0 < NACG) ? mh*(-expf(P_lacgbc[bc*NACG+j0]))
                          : ((j0 >= 36) ? mh*(-expf(P_laclbc[bc*NACL+(j0-36)])) : 0.f);
                float w1 = (j1 < NACG) ? mh*(-expf(P_lacgbc[bc*NACG+j1]))
                          : ((j1 >= 36) ? mh*(-expf(P_laclbc[bc*NACL+(j1-36)])) : 0.f);
                wFB[k] = pk(w0, w1);
            }
        }
        const float* gq = sm_B + ((l & 16) ? 20 : 0);
        float* gRow = ringG + l*53;
        __syncwarp();

        uint64_t S12 = 0, G12 = 0;
        float cvS = cS, baseG = cgG;
        LOADCHUNK(0); STORECHUNK(0); LOADCHUNK(1);
        __syncwarp();
        for (int c = 0; c < NCHUNK; c++){
            int cur = c & 1;
            STORECHUNK(cur^1);
            int nk = (c+2 < NCHUNK) ? (c+2) : (NCHUNK-1);
            LOADCHUNK(nk);
            __syncwarp();
            const float* db = dbuf[cur];
            int tbase = c*16;
            #pragma unroll 2
            for (int i = 0; i < 16; i++){
                /* ---- off-chain top ---- */
                float yoS = secPtr[ri];
                float yoG = gRow[ri];
                float xi  = prim ? db[i*NBC + l] : 0.f;
                float fbBase = fmaf(mBC, xi, cP);
                float t12 = c_p12*ip*(1.0f - rrp*c_irrp);
                float ip_n = ip + c_p01*(c_ipcap - ip) - t12;
                float rrp_m = rrp + t12;
                uint64_t pbS = fma2(nkSc2, pk(yoS,yoS), mul2(rS2p, S12));
                uint64_t pbG = fma2(nkGc2, pk(yoG,yoG), mul2(rG2p, G12));
                float b1,b2; upk(pbS,b1,b2); float bDS = (b1-b2)+cS;
                upk(pbG,b1,b2); float bDG = (b1-b2)+cgG;
                /* ---- stage 1: Sec tanh (valid for A lanes) ---- */
                float tvS = ftanh(cvS);
                sm_B[secSlot] = tvS;
                __syncwarp();
                /* ---- stage 2: ACG pre-activations from tvA (sm_B[36..45]) ---- */
                uint64_t t0 = ld64s(sm_B+36), t1 = ld64s(sm_B+38),
                         t2 = ld64s(sm_B+40), t3 = ld64s(sm_B+42),
                         t4 = ld64s(sm_B+44);
                uint64_t pg0 = pk(baseG, 0.f);
                uint64_t pg1 = mul2(wGa2[1], t1);
                pg0 = fma2(wGa2[0], t0, pg0);
                pg1 = fma2(wGa2[2], t2, pg1);
                pg0 = fma2(wGa2[3], t3, pg0);
                pg1 = fma2(wGa2[4], t4, pg1);
                uint64_t ph0 = pk(cvS, 0.f);
                uint64_t ph1 = mul2(wHa2[1], t1);
                ph0 = fma2(wHa2[0], t0, ph0);
                ph1 = fma2(wHa2[2], t2, ph1);
                ph0 = fma2(wHa2[3], t3, ph0);
                ph1 = fma2(wHa2[4], t4, ph1);
                float x0,x1,x2,x3;
                upk(pg0,x0,x1); upk(pg1,x2,x3);
                float tvG = ftanh((x0+x1)+(x2+x3));
                upk(ph0,x0,x1); upk(ph1,x2,x3);
                float tvH = ftanh((x0+x1)+(x2+x3));
                sm_B[l] = tvG;
                sm_B[hSlot] = tvH;
                __syncwarp();
                /* ---- stage 3: BC pre-activation, half-split, 13 packed taps each ---- */
                uint64_t q0 = ld64s(gq+0),  q1 = ld64s(gq+2),  q2 = ld64s(gq+4),
                         q3 = ld64s(gq+6),  q4 = ld64s(gq+8),  q5 = ld64s(gq+10),
                         q6 = ld64s(gq+12), q7 = ld64s(gq+14), q8 = ld64s(gq+16),
                         q9 = ld64s(gq+18), q10 = ld64s(gq+20), q11 = ld64s(gq+22),
                         q12 = ld64s(gq+24);
                uint64_t s0 = pk(fbBase, 0.f);
                uint64_t s1 = mul2(wFB[1], q1);
                uint64_t s2 = mul2(wFB[2], q2);
                s0 = fma2(wFB[0], q0, s0);
                s0 = fma2(wFB[3], q3, s0);
                s1 = fma2(wFB[4], q4, s1);
                s2 = fma2(wFB[5], q5, s2);
                s0 = fma2(wFB[6], q6, s0);
                s1 = fma2(wFB[7], q7, s1);
                s2 = fma2(wFB[8], q8, s2);
                s0 = fma2(wFB[9], q9, s0);
                s1 = fma2(wFB[10], q10, s1);
                s2 = fma2(wFB[11], q11, s2);
                s0 = fma2(wFB[12], q12, s0);
                float u0,u1,u2,u3,u4,u5;
                upk(s0,u0,u1); upk(s1,u2,u3); upk(s2,u4,u5);
                float s_loc = ((u0+u1)+(u2+u3))+(u4+u5);
                float s_oth = __shfl_down_sync(FULLM, s_loc, 16);
                float e = fex2(s_loc + s_oth);
                float relv = rrp * frcp(1.0f + e);
                ip = ip_n; rrp = rrp_m - relv;
                if (prim){ relrow[tbase+i] = relv; sm_rel[l] = relv; }
                __syncwarp();
                /* ---- stage 4: two packed matvecs (yG for all, ySec for A/H) ---- */
                uint64_t rp0 = ld64s(sm_rel+0), rp1 = ld64s(sm_rel+2),
                         rp2 = ld64s(sm_rel+4), rp3 = ld64s(sm_rel+6),
                         rp4 = ld64s(sm_rel+8), rp5 = ld64s(sm_rel+10),
                         rp6 = ld64s(sm_rel+12);
                uint64_t ga = mul2(wyG2[0], rp0);
                uint64_t gb = mul2(wyG2[1], rp1);
                ga = fma2(wyG2[2], rp2, ga);
                gb = fma2(wyG2[3], rp3, gb);
                ga = fma2(wyG2[4], rp4, ga);
                gb = fma2(wyG2[5], rp5, gb);
                ga = fma2(wyG2[6], rp6, ga);
                uint64_t sa = mul2(wyS2[0], rp0);
                uint64_t sb = mul2(wyS2[1], rp1);
                sa = fma2(wyS2[2], rp2, sa);
                sb = fma2(wyS2[3], rp3, sb);
                sa = fma2(wyS2[4], rp4, sa);
                sb = fma2(wyS2[5], rp5, sb);
                sa = fma2(wyS2[6], rp6, sa);
                float v0,v1,v2,v3;
                upk(ga,v0,v1); upk(gb,v2,v3);
                float yG = (v0+v1)+(v2+v3);
                upk(sa,v0,v1); upk(sb,v2,v3);
                float yS = (v0+v1)+(v2+v3);
                cvS   = fmaf(dkS, yS, bDS);
                baseG = fmaf(dkG, yG, bDG);
                gRow[ri] = yG;
                secPtr[ri] = yS;
                S12 = fma2(kS12p, pk(yS,yS), pbS);
                G12 = fma2(kG12p, pk(yG,yG), pbG);
                ri = (ri == KACN-1) ? 0 : ri+1;
            }
            __syncwarp();
        }
    }
#undef LOADCHUNK
#undef STORECHUNK
}

// ---------------- iGluSnFR readout: 32-tap FIR over rel ----------------
__global__ void out_kernel(float* __restrict__ out){
    __shared__ float skg[K1];
    int tid = threadIdx.x;
    if (tid < K1) skg[tid] = g_kglu[tid];
    __syncthreads();
    int oid = blockIdx.x*blockDim.x + tid;
    if (oid >= 2*NBC*TN) return;
    int n  = oid & (TN-1);
    int pc = oid >> 15;
    const float* r = g_rel + pc*RELSTRIDE + n;
    float a0 = 0.f, a1 = 0.f;
    #pragma unroll
    for (int j = 0; j < K1; j++){
        float v = r[K1-1-j];
        if (j & 1) a1 = fmaf(skg[j], v, a1);
        else       a0 = fmaf(skg[j], v, a0);
    }
    out[oid] = a0 + a1;
}

extern "C" void kernel_launch(void* const* d_in, const int* in_sizes, int n_in,
                              void* d_out, int out_size){
    (void)in_sizes; (void)n_in; (void)out_size;
    const float* x  = (const float*)d_in[0];
    const float* sb = (const float*)d_in[1];
    const float* ss = (const float*)d_in[2];

    setup_kernel<<<1, 64>>>((const float*)d_in[3]);
    xp_kernel<<<(XPLEN+255)/256, 256>>>(x, sb, ss);
    drive_kernel<<<(NSTEPS+127)/128, 128>>>();
    scan_kernel<<<2, 32>>>(
        (const float*)d_in[4],  (const float*)d_in[5],
        (const float*)d_in[6],  (const float*)d_in[7],
        (const float*)d_in[8],  (const float*)d_in[9],
        (const float*)d_in[10], (const float*)d_in[11],
        (const float*)d_in[12], (const float*)d_in[13],
        (const float*)d_in[14], (const float*)d_in[15],
        (const float*)d_in[16], (const float*)d_in[17],
        (const float*)d_in[18], (const float*)d_in[19],
        (const float*)d_in[20], (const float*)d_in[21],
        (const float*)d_in[22], (const float*)d_in[23],
        (const float*)d_in[24], (const float*)d_in[25]);
    out_kernel<<<(2*NBC*TN+255)/256, 256>>>((float*)d_out);
}

// round 8
// speedup vs baseline: 1.7383x; 1.0346x over previous
#include <cuda_runtime.h>
#include <cstdint>

#define TN 32768
#define TLOOP 32799
#define NCHUNK 2050
#define NSTEPS (NCHUNK*16)   /* 32800 */
#define NBC 14
#define NACL 10
#define NACG 35
#define KACN 52
#define K0 20
#define K1 32
#define PADL 50              /* (K0-1)+(K1-1) */
#define XPLEN (TN + PADL)    /* 32818 */
#define RELSTRIDE 32832
#define FULLM 0xffffffffu

__device__ float g_xp[XPLEN];
__device__ float g_drive[NSTEPS*NBC];
__device__ float g_rel[2*NBC*RELSTRIDE];
__device__ float g_kbc[NBC*K0];
__device__ float g_kglu[K1];

__device__ __forceinline__ float ftanh(float x){
    float y; asm("tanh.approx.f32 %0, %1;" : "=f"(y) : "f"(x)); return y;
}
__device__ __forceinline__ float fex2(float x){
    float y; asm("ex2.approx.f32 %0, %1;" : "=f"(y) : "f"(x)); return y;
}
__device__ __forceinline__ float frcp(float x){
    float y; asm("rcp.approx.f32 %0, %1;" : "=f"(y) : "f"(x)); return y;
}
/* ---- packed fp32x2 ops (FFMA2 path, full fp32 precision) ---- */
__device__ __forceinline__ uint64_t pk(float lo, float hi){
    uint64_t r; asm("mov.b64 %0, {%1,%2};" : "=l"(r) : "f"(lo), "f"(hi)); return r;
}
__device__ __forceinline__ void upk(uint64_t v, float &lo, float &hi){
    asm("mov.b64 {%0,%1}, %2;" : "=f"(lo), "=f"(hi) : "l"(v));
}
__device__ __forceinline__ uint64_t fma2(uint64_t a, uint64_t b, uint64_t c){
    uint64_t d; asm("fma.rn.f32x2 %0, %1, %2, %3;" : "=l"(d) : "l"(a), "l"(b), "l"(c)); return d;
}
__device__ __forceinline__ uint64_t mul2(uint64_t a, uint64_t b){
    uint64_t d; asm("mul.rn.f32x2 %0, %1, %2;" : "=l"(d) : "l"(a), "l"(b)); return d;
}
/* ---- ordered shared-memory ops (warp-synchronous broadcast, no barrier):
   producer STS sits at a warp-CONVERGED point (branch-free slot-select), the
   in-order smem pipe guarantees a later LDS of the same warp sees it; the
   asm volatile + memory clobbers pin compiler ordering. ---- */
__device__ __forceinline__ void sts32(float* p, float v){
    uint32_t a = (uint32_t)__cvta_generic_to_shared(p);
    asm volatile("st.shared.f32 [%0], %1;" :: "r"(a), "f"(v) : "memory");
}
__device__ __forceinline__ uint64_t ld64sv(const float* p){
    uint32_t a = (uint32_t)__cvta_generic_to_shared(p);
    uint64_t r;
    asm volatile("ld.shared.b64 %0, [%1];" : "=l"(r) : "r"(a) : "memory");
    return r;
}

// double-exponential AC kernel -> IIR coefficients (exact FIR-equivalent with
// truncation correction): kern(L) = A*r1^L - B*r2^L (L=0 newest), L2-normalized
__device__ __forceinline__ void ac_coef(float ltr, float ltd,
    float &A, float &B, float &r1, float &r2, float &c1, float &c2){
    float tr = expf(ltr), td = expf(ltd);
    float beta = (td + tr) / (td * tr);
    float n2 = 0.f;
    for (int k = 0; k < KACN; k++){
        float t = 0.8f - (float)k * (1.0f/64.0f);
        float v = expf(-t/td) - expf(-beta*t);
        n2 = fmaf(v, v, n2);
    }
    float inv = 1.0f / sqrtf(n2);
    const float c0 = 0.8f - 51.0f*(1.0f/64.0f);
    A  = expf(-c0/td) * inv;
    B  = expf(-beta*c0) * inv;
    r1 = expf(-1.0f/(64.0f*td));
    r2 = expf(-beta*(1.0f/64.0f));
    c1 = expf(-0.8125f/td);        /* r1^52 */
    c2 = expf(-beta*0.8125f);      /* r2^52 */
}

// ---------------- setup: BC biphasic kernels + iGluSnFR kernel ----------------
__global__ void setup_kernel(const float* __restrict__ lks){
    int t = threadIdx.x;
    if (t < NBC){
        float speed = expf(lks[t]);
        float ct = (t < 5) ? -1.0f : 1.0f;
        float vals[K0]; float n2 = 0.f;
        #pragma unroll
        for (int j = 0; j < K0; j++){
            float ts = (float)j * (1.0f/64.0f) * speed;
            float a = ts / 0.05f, b = ts / 0.1f;
            float v = a*a*expf(-a) - 0.8f*b*b*expf(-b);
            v *= ct;
            vals[j] = v; n2 += v*v;
        }
        float inv = 1.0f / sqrtf(n2);
        #pragma unroll
        for (int j = 0; j < K0; j++) g_kbc[t*K0+j] = vals[j]*inv;
    }
    if (t == 32){
        float vals[K1]; float s = 0.f;
        #pragma unroll
        for (int j = 0; j < K1; j++){
            float tg = (float)j * (1.0f/64.0f);
            float v = (1.0f - expf(-tg/0.02f)) * expf(-tg/0.1f);
            vals[j] = v; s += v;
        }
        #pragma unroll
        for (int j = 0; j < K1; j++) g_kglu[j] = vals[j]/s;
    }
}

// ---------------- stimulus affine + edge padding ----------------
__global__ void xp_kernel(const float* __restrict__ x,
                          const float* __restrict__ sb,
                          const float* __restrict__ ss){
    int i = blockIdx.x*blockDim.x + threadIdx.x;
    if (i >= XPLEN) return;
    float es = expf(ss[0]); float b = sb[0];
    int s = i - PADL; if (s < 0) s = 0;
    g_xp[i] = x[s]*es + b;
}

// ---------------- per-BC 20-tap FIR -> drive[NSTEPS][NBC] ----------------
__global__ void drive_kernel(){
    __shared__ float skb[NBC*K0];
    int tid = threadIdx.x;
    for (int i = tid; i < NBC*K0; i += blockDim.x) skb[i] = g_kbc[i];
    __syncthreads();
    int n = blockIdx.x*blockDim.x + tid;
    if (n >= NSTEPS) return;
    if (n >= TLOOP){
        #pragma unroll
        for (int c = 0; c < NBC; c++) g_drive[n*NBC+c] = 0.f;
        return;
    }
    float xw[K0];
    #pragma unroll
    for (int j = 0; j < K0; j++) xw[j] = g_xp[n + j];
    #pragma unroll
    for (int c = 0; c < NBC; c++){
        float a0 = 0.f, a1 = 0.f;
        #pragma unroll
        for (int j = 0; j < K0; j++){
            float w = skb[c*K0+j];
            float v = xw[K0-1-j];
            if (j & 1) a1 = fmaf(w, v, a1); else a0 = fmaf(w, v, a0);
        }
        g_drive[n*NBC+c] = a0 + a1;
    }
}

// ---------------- the sequential scan: 2 blocks (pathways) x 1 warp ----------------
__global__ void __launch_bounds__(32,1) scan_kernel(
    const float* __restrict__ P_sigoff, const float* __restrict__ P_lslope,
    const float* __restrict__ P_lp01,  const float* __restrict__ P_lp12,
    const float* __restrict__ P_lipc,  const float* __restrict__ P_lrrpc,
    const float* __restrict__ P_ipst,  const float* __restrict__ P_rrpst,
    const float* __restrict__ P_laclbc, const float* __restrict__ P_lbcacl,
    const float* __restrict__ P_acltr, const float* __restrict__ P_acltd,
    const float* __restrict__ P_aclsl, const float* __restrict__ P_aclof,
    const float* __restrict__ P_lacgbc, const float* __restrict__ P_lbcacg,
    const float* __restrict__ P_acgtr, const float* __restrict__ P_acgtd,
    const float* __restrict__ P_acgsl, const float* __restrict__ P_acgof,
    const float* __restrict__ P_laclacg, const float* __restrict__ P_bcnoff)
{
    const int path = blockIdx.x;
    const int l = threadIdx.x;
    __shared__ float ringA[11*53];          /* rows 0-9 ACL, row 10 dummy */
    __shared__ float ringG[NACG*53];
    __shared__ float dbuf[2][16*NBC];
    __shared__ __align__(16) float sm_B[48];   /* [0..34] tvG/tvH, [35]=0, [36..45] tvA, [46..47] dummy */
    __shared__ __align__(16) float sm_tvA[12]; /* LNR only; [10..11] dummy */
    __shared__ __align__(16) float sm_rel[48]; /* [0..13] rel, [14..15]=0, [16..47] scratch */
    for (int i = l; i < 11*53; i += 32) ringA[i] = 0.f;
    for (int i = l; i < NACG*53; i += 32) ringG[i] = 0.f;
    { if (l < 48) sm_B[l] = 0.f; if (l+32 < 48) sm_B[l+32] = 0.f; }
    if (l < 12) sm_tvA[l] = 0.f;
    { if (l < 48) sm_rel[l] = 0.f; if (l+32 < 48) sm_rel[l+32] = 0.f; }

    const bool prim = (l < NBC);
    const int bc = prim ? l : ((l >= 16 && l < 16+NBC) ? (l-16) : -1);
    const int relSlot = prim ? l : (16 + l);          /* scratch for idle lanes */

    // ---- BC pool role (prim lanes, both paths) ----
    float cP=0.f, mBC=0.f, c_p01=0.f, c_p12=0.f, c_ipcap=0.f, c_irrp=0.f;
    float ip=0.f, rrp=0.f;
    float mh = 0.f;
    if (bc >= 0) mh = -0.5f*1.44269504f*expf(P_lslope[bc]);
    if (prim){
        float off   = P_sigoff[l] + (path ? P_bcnoff[l] : 0.f);
        mBC = 2.0f*mh;
        c_p01   = expf(P_lp01[l]);
        c_p12   = expf(P_lp12[l]);
        c_ipcap = expf(P_lipc[l]);
        float rc = expf(P_lrrpc[l]);
        c_irrp = 1.0f / rc;
        ip  = c_ipcap / (1.0f + expf(-P_ipst[l]));
        rrp = rc      / (1.0f + expf(-P_rrpst[l]));
        float sA = 0.f, sG = 0.f;
        #pragma unroll
        for (int j = 0; j < NACL; j++) sA += -expf(P_laclbc[l*NACL+j]);
        if (path){
            #pragma unroll
            for (int j = 0; j < NACG; j++) sG += -expf(P_lacgbc[l*NACG+j]);
        }
        cP = mBC*(0.5f*(sA+sG) - off);
    }

    float* relrow = g_rel + (path*NBC + (prim ? l : 0))*RELSTRIDE;
    int ri = 0;

    float fd0,fd1,fd2,fd3,fd4,fd5,fd6;
#define LOADCHUNK(k) do{ const float* _p = g_drive + (k)*224 + l; \
        fd0=_p[0]; fd1=_p[32]; fd2=_p[64]; fd3=_p[96]; fd4=_p[128]; fd5=_p[160]; fd6=_p[192]; }while(0)
#define STORECHUNK(bi) do{ float* _q = dbuf[bi] + l; \
        _q[0]=fd0; _q[32]=fd1; _q[64]=fd2; _q[96]=fd3; _q[128]=fd4; _q[160]=fd5; _q[192]=fd6; }while(0)

    if (path == 0){
        // ================= LNR pathway =================
        uint64_t wA2[5];
        #pragma unroll
        for (int k = 0; k < 5; k++) wA2[k] = 0;
        if (prim){
            #pragma unroll
            for (int k = 0; k < 5; k++){
                float w0 = -expf(P_laclbc[l*NACL+2*k]);
                float w1 = -expf(P_laclbc[l*NACL+2*k+1]);
                wA2[k] = pk(mh*w0, mh*w1);
            }
        }
        uint64_t rA2p=0, nkAc2=0, kA12p=0, wyA2[7];
        float caA=0.f, dkA=0.f;
        #pragma unroll
        for (int k = 0; k < 7; k++) wyA2[k] = 0;
        if (l < NACL){
            float A,B,r1,r2,c1,c2;
            ac_coef(P_acltr[l], P_acltd[l], A,B,r1,r2,c1,c2);
            float ha = 0.5f*expf(P_aclsl[l]);
            float kA1 = ha*A, kA2 = ha*B;
            rA2p  = pk(r1, r2);
            nkAc2 = pk(-kA1*c1, -kA2*c2);
            kA12p = pk(kA1, kA2);
            caA = -ha*P_aclof[l];
            dkA = kA1 - kA2;
            #pragma unroll
            for (int k = 0; k < 7; k++)
                wyA2[k] = pk(expf(P_lbcacl[l*NBC+2*k]), expf(P_lbcacl[l*NBC+2*k+1]));
        }
        const int tvASlot = (l < NACL) ? l : 10;
        __syncwarp();
        uint64_t A12 = 0;
        float cvA = caA;
        LOADCHUNK(0); STORECHUNK(0); LOADCHUNK(1);
        __syncwarp();
        for (int c = 0; c < NCHUNK; c++){
            int cur = c & 1;
            STORECHUNK(cur^1);
            int nk = (c+2 < NCHUNK) ? (c+2) : (NCHUNK-1);
            LOADCHUNK(nk);
            __syncwarp();
            const float* db = dbuf[cur];
            int tbase = c*16;
            #pragma unroll 4
            for (int i = 0; i < 16; i++){
                float yoA = (l < NACL) ? ringA[l*53+ri] : 0.f;
                float xi  = prim ? db[i*NBC + l] : 0.f;
                float fbBase = fmaf(mBC, xi, cP);
                float t12 = c_p12*ip*(1.0f - rrp*c_irrp);
                float ip_n = ip + c_p01*(c_ipcap - ip) - t12;
                float rrp_m = rrp + t12;
                uint64_t pbA = fma2(nkAc2, pk(yoA,yoA), mul2(rA2p, A12));
                float bA1, bA2; upk(pbA, bA1, bA2);
                float bDA = (bA1 - bA2) + caA;
                float tvA = ftanh(cvA);
                sts32(sm_tvA + tvASlot, tvA);           /* converged STS */
                uint64_t tp0 = ld64sv(sm_tvA+0), tp1 = ld64sv(sm_tvA+2),
                         tp2 = ld64sv(sm_tvA+4), tp3 = ld64sv(sm_tvA+6),
                         tp4 = ld64sv(sm_tvA+8);
                uint64_t f0 = pk(fbBase, 0.f);
                uint64_t f1 = mul2(wA2[1], tp1);
                f0 = fma2(wA2[0], tp0, f0);
                f1 = fma2(wA2[2], tp2, f1);
                f0 = fma2(wA2[3], tp3, f0);
                f1 = fma2(wA2[4], tp4, f1);
                float a0,a1,a2,a3; upk(f0,a0,a1); upk(f1,a2,a3);
                float e = fex2((a0+a1)+(a2+a3));
                float relv = rrp * frcp(1.0f + e);
                ip = ip_n; rrp = rrp_m - relv;
                sts32(sm_rel + relSlot, relv);          /* converged STS */
                if (prim) relrow[tbase+i] = relv;       /* divergent AFTER sts */
                uint64_t rp0 = ld64sv(sm_rel+0), rp1 = ld64sv(sm_rel+2),
                         rp2 = ld64sv(sm_rel+4), rp3 = ld64sv(sm_rel+6),
                         rp4 = ld64sv(sm_rel+8), rp5 = ld64sv(sm_rel+10),
                         rp6 = ld64sv(sm_rel+12);
                uint64_t y0 = mul2(wyA2[0], rp0);
                uint64_t y1 = mul2(wyA2[1], rp1);
                y0 = fma2(wyA2[2], rp2, y0);
                y1 = fma2(wyA2[3], rp3, y1);
                y0 = fma2(wyA2[4], rp4, y0);
                y1 = fma2(wyA2[5], rp5, y1);
                y0 = fma2(wyA2[6], rp6, y0);
                float v0,v1,v2,v3; upk(y0,v0,v1); upk(y1,v2,v3);
                float yA = (v0+v1)+(v2+v3);
                cvA = fmaf(dkA, yA, bDA);
                if (l < NACL) ringA[l*53+ri] = yA;
                A12 = fma2(kA12p, pk(yA,yA), pbA);
                ri = (ri == KACN-1) ? 0 : ri+1;
            }
            __syncwarp();
        }
    } else {
        // ================= BCN pathway: no-sync broadcast + all-primary stage3 =================
        const bool isA = (l >= 16 && l < 26);
        const bool isH = (l < 3);
        // ---- G channel (every lane owns ACG channel l) ----
        uint64_t rG2p, nkGc2, kG12p, wGa2[5], wyG2[7];
        float cgG, dkG;
        {
            float A,B,r1,r2,c1,c2;
            ac_coef(P_acgtr[l], P_acgtd[l], A,B,r1,r2,c1,c2);
            float hg = 0.5f*expf(P_acgsl[l]);
            float k1 = hg*A, k2 = hg*B;
            rG2p  = pk(r1, r2);
            nkGc2 = pk(-k1*c1, -k2*c2);
            kG12p = pk(k1, k2);
            dkG = k1 - k2;
            float sw = 0.f;
            #pragma unroll
            for (int k = 0; k < 5; k++){
                float w0 = -expf(P_laclacg[l*NACL+2*k]);
                float w1 = -expf(P_laclacg[l*NACL+2*k+1]);
                sw += w0 + w1;
                wGa2[k] = pk(hg*0.5f*w0, hg*0.5f*w1);
            }
            cgG = hg*(0.5f*sw - P_acgof[l]);
            #pragma unroll
            for (int k = 0; k < 7; k++)
                wyG2[k] = pk(expf(P_lbcacg[l*NBC+2*k]), expf(P_lbcacg[l*NBC+2*k+1]));
        }
        // ---- Sec channel: A on lanes 16-25, H(=ACG 32-34) on lanes 0-2 ----
        uint64_t rS2p=0, nkSc2=0, kS12p=0, wyS2[7], wHa2[5];
        float cS=0.f, dkS=0.f;
        float* secPtr = ringA + 10*53;
        #pragma unroll
        for (int k = 0; k < 7; k++) wyS2[k] = 0;
        #pragma unroll
        for (int k = 0; k < 5; k++) wHa2[k] = 0;
        if (isA){
            int a = l - 16;
            float A,B,r1,r2,c1,c2;
            ac_coef(P_acltr[a], P_acltd[a], A,B,r1,r2,c1,c2);
            float ha = 0.5f*expf(P_aclsl[a]);
            float k1 = ha*A, k2 = ha*B;
            rS2p = pk(r1,r2); nkSc2 = pk(-k1*c1,-k2*c2); kS12p = pk(k1,k2);
            dkS = k1 - k2;
            cS = -ha*P_aclof[a];
            #pragma unroll
            for (int k = 0; k < 7; k++)
                wyS2[k] = pk(expf(P_lbcacl[a*NBC+2*k]), expf(P_lbcacl[a*NBC+2*k+1]));
            secPtr = ringA + a*53;
        } else if (isH){
            int h = l + 32;
            float A,B,r1,r2,c1,c2;
            ac_coef(P_acgtr[h], P_acgtd[h], A,B,r1,r2,c1,c2);
            float hh = 0.5f*expf(P_acgsl[h]);
            float k1 = hh*A, k2 = hh*B;
            rS2p = pk(r1,r2); nkSc2 = pk(-k1*c1,-k2*c2); kS12p = pk(k1,k2);
            dkS = k1 - k2;
            float swh = 0.f;
            #pragma unroll
            for (int k = 0; k < 5; k++){
                float w0 = -expf(P_laclacg[h*NACL+2*k]);
                float w1 = -expf(P_laclacg[h*NACL+2*k+1]);
                swh += w0 + w1;
                wHa2[k] = pk(hh*0.5f*w0, hh*0.5f*w1);
            }
            cS = hh*(0.5f*swh - P_acgof[h]);
            #pragma unroll
            for (int k = 0; k < 7; k++)
                wyS2[k] = pk(expf(P_lbcacg[h*NBC+2*k]), expf(P_lbcacg[h*NBC+2*k+1]));
            secPtr = ringG + h*53;
        }
        const int secSlot = isA ? (36 + (l-16)) : 46;
        const int hSlot   = isH ? (32 + l) : 46;
        // ---- BC feedback: ALL 36 ACG taps (35 + pad) on primary lanes, packed ----
        uint64_t wFB[18], wA2[5];
        #pragma unroll
        for (int k = 0; k < 18; k++) wFB[k] = 0;
        #pragma unroll
        for (int k = 0; k < 5; k++) wA2[k] = 0;
        if (prim){
            #pragma unroll
            for (int k = 0; k < 18; k++){
                int j0 = 2*k, j1 = 2*k+1;
                float w0 = (j0 < NACG) ? mh*(-expf(P_lacgbc[l*NACG+j0])) : 0.f;
                float w1 = (j1 < NACG) ? mh*(-expf(P_lacgbc[l*NACG+j1])) : 0.f;
                wFB[k] = pk(w0, w1);
            }
            #pragma unroll
            for (int k = 0; k < 5; k++){
                float w0 = -expf(P_laclbc[l*NACL+2*k]);
                float w1 = -expf(P_laclbc[l*NACL+2*k+1]);
                wA2[k] = pk(mh*w0, mh*w1);
            }
        }
        float* gRow = ringG + l*53;
        __syncwarp();

        uint64_t S12 = 0, G12 = 0;
        float cvS = cS, baseG = cgG;
        LOADCHUNK(0); STORECHUNK(0); LOADCHUNK(1);
        __syncwarp();
        for (int c = 0; c < NCHUNK; c++){
            int cur = c & 1;
            STORECHUNK(cur^1);
            int nk = (c+2 < NCHUNK) ? (c+2) : (NCHUNK-1);
            LOADCHUNK(nk);
            __syncwarp();
            const float* db = dbuf[cur];
            int tbase = c*16;
            #pragma unroll 2
            for (int i = 0; i < 16; i++){
                /* ---- off-chain top ---- */
                float yoS = secPtr[ri];
                float yoG = gRow[ri];
                float xi  = prim ? db[i*NBC + l] : 0.f;
                float fbBase = fmaf(mBC, xi, cP);
                float t12 = c_p12*ip*(1.0f - rrp*c_irrp);
                float ip_n = ip + c_p01*(c_ipcap - ip) - t12;
                float rrp_m = rrp + t12;
                uint64_t pbS = fma2(nkSc2, pk(yoS,yoS), mul2(rS2p, S12));
                uint64_t pbG = fma2(nkGc2, pk(yoG,yoG), mul2(rG2p, G12));
                float b1,b2; upk(pbS,b1,b2); float bDS = (b1-b2)+cS;
                upk(pbG,b1,b2); float bDG = (b1-b2)+cgG;
                /* ---- stage 1: Sec tanh, converged slot-select STS ---- */
                float tvS = ftanh(cvS);
                sts32(sm_B + secSlot, tvS);
                /* ---- stage 2: ACG pre-activations from tvA (sm_B[36..45]) ---- */
                uint64_t t0 = ld64sv(sm_B+36), t1 = ld64sv(sm_B+38),
                         t2 = ld64sv(sm_B+40), t3 = ld64sv(sm_B+42),
                         t4 = ld64sv(sm_B+44);
                uint64_t pg0 = pk(baseG, 0.f);
                uint64_t pg1 = mul2(wGa2[1], t1);
                pg0 = fma2(wGa2[0], t0, pg0);
                pg1 = fma2(wGa2[2], t2, pg1);
                pg0 = fma2(wGa2[3], t3, pg0);
                pg1 = fma2(wGa2[4], t4, pg1);
                uint64_t ph0 = pk(cvS, 0.f);
                uint64_t ph1 = mul2(wHa2[1], t1);
                ph0 = fma2(wHa2[0], t0, ph0);
                ph1 = fma2(wHa2[2], t2, ph1);
                ph0 = fma2(wHa2[3], t3, ph0);
                ph1 = fma2(wHa2[4], t4, ph1);
                /* ACL->BC partials on prim lanes, reusing t0..t4 (tanhG shadow) */
                uint64_t ae0 = mul2(wA2[0], t0);
                uint64_t ae1 = mul2(wA2[1], t1);
                ae0 = fma2(wA2[2], t2, ae0);
                ae1 = fma2(wA2[3], t3, ae1);
                ae0 = fma2(wA2[4], t4, ae0);
                float x0,x1,x2,x3;
                upk(pg0,x0,x1); upk(pg1,x2,x3);
                float tvG = ftanh((x0+x1)+(x2+x3));
                upk(ph0,x0,x1); upk(ph1,x2,x3);
                float tvH = ftanh((x0+x1)+(x2+x3));
                sts32(sm_B + l, tvG);                   /* converged */
                sts32(sm_B + hSlot, tvH);               /* converged */
                /* ---- stage 3: all 36 ACG taps on prim lanes, 4 accums ---- */
                uint64_t s0 = pk(fbBase, 0.f);
                uint64_t s1 = ae0;
                uint64_t s2 = ae1;
                uint64_t q0 = ld64sv(sm_B+0),  q1 = ld64sv(sm_B+2),
                         q2 = ld64sv(sm_B+4),  q3 = ld64sv(sm_B+6);
                uint64_t s3 = mul2(wFB[3], q3);
                s0 = fma2(wFB[0], q0, s0);
                s1 = fma2(wFB[1], q1, s1);
                s2 = fma2(wFB[2], q2, s2);
                uint64_t q4 = ld64sv(sm_B+8),  q5 = ld64sv(sm_B+10),
                         q6 = ld64sv(sm_B+12), q7 = ld64sv(sm_B+14);
                s0 = fma2(wFB[4], q4, s0);
                s1 = fma2(wFB[5], q5, s1);
                s2 = fma2(wFB[6], q6, s2);
                s3 = fma2(wFB[7], q7, s3);
                uint64_t q8 = ld64sv(sm_B+16),  q9 = ld64sv(sm_B+18),
                         q10 = ld64sv(sm_B+20), q11 = ld64sv(sm_B+22);
                s0 = fma2(wFB[8], q8, s0);
                s1 = fma2(wFB[9], q9, s1);
                s2 = fma2(wFB[10], q10, s2);
                s3 = fma2(wFB[11], q11, s3);
                uint64_t q12 = ld64sv(sm_B+24), q13 = ld64sv(sm_B+26),
                         q14 = ld64sv(sm_B+28), q15 = ld64sv(sm_B+30);
                s0 = fma2(wFB[12], q12, s0);
                s1 = fma2(wFB[13], q13, s1);
                s2 = fma2(wFB[14], q14, s2);
                s3 = fma2(wFB[15], q15, s3);
                uint64_t q16 = ld64sv(sm_B+32), q17 = ld64sv(sm_B+34);
                s0 = fma2(wFB[16], q16, s0);
                s1 = fma2(wFB[17], q17, s1);
                float u0,u1,u2,u3,u4,u5,u6,u7;
                upk(s0,u0,u1); upk(s1,u2,u3); upk(s2,u4,u5); upk(s3,u6,u7);
                float s = ((u0+u1)+(u2+u3)) + ((u4+u5)+(u6+u7));
                float e = fex2(s);
                float relv = rrp * frcp(1.0f + e);
                ip = ip_n; rrp = rrp_m - relv;
                sts32(sm_rel + relSlot, relv);          /* converged */
                if (prim) relrow[tbase+i] = relv;       /* divergent AFTER sts */
                /* ---- stage 4: two packed matvecs (yG for all, ySec for A/H) ---- */
                uint64_t rp0 = ld64sv(sm_rel+0), rp1 = ld64sv(sm_rel+2),
                         rp2 = ld64sv(sm_rel+4), rp3 = ld64sv(sm_rel+6),
                         rp4 = ld64sv(sm_rel+8), rp5 = ld64sv(sm_rel+10),
                         rp6 = ld64sv(sm_rel+12);
                uint64_t ga = mul2(wyG2[0], rp0);
                uint64_t gb = mul2(wyG2[1], rp1);
                ga = fma2(wyG2[2], rp2, ga);
                gb = fma2(wyG2[3], rp3, gb);
                ga = fma2(wyG2[4], rp4, ga);
                gb = fma2(wyG2[5], rp5, gb);
                ga = fma2(wyG2[6], rp6, ga);
                uint64_t sa = mul2(wyS2[0], rp0);
                uint64_t sb = mul2(wyS2[1], rp1);
                sa = fma2(wyS2[2], rp2, sa);
                sb = fma2(wyS2[3], rp3, sb);
                sa = fma2(wyS2[4], rp4, sa);
                sb = fma2(wyS2[5], rp5, sb);
                sa = fma2(wyS2[6], rp6, sa);
                float v0,v1,v2,v3;
                upk(ga,v0,v1); upk(gb,v2,v3);
                float yG = (v0+v1)+(v2+v3);
                upk(sa,v0,v1); upk(sb,v2,v3);
                float yS = (v0+v1)+(v2+v3);
                cvS   = fmaf(dkS, yS, bDS);
                baseG = fmaf(dkG, yG, bDG);
                gRow[ri] = yG;
                secPtr[ri] = yS;
                S12 = fma2(kS12p, pk(yS,yS), pbS);
                G12 = fma2(kG12p, pk(yG,yG), pbG);
                ri = (ri == KACN-1) ? 0 : ri+1;
            }
            __syncwarp();
        }
    }
#undef LOADCHUNK
#undef STORECHUNK
}

// ---------------- iGluSnFR readout: 32-tap FIR over rel ----------------
__global__ void out_kernel(float* __restrict__ out){
    __shared__ float skg[K1];
    int tid = threadIdx.x;
    if (tid < K1) skg[tid] = g_kglu[tid];
    __syncthreads();
    int oid = blockIdx.x*blockDim.x + tid;
    if (oid >= 2*NBC*TN) return;
    int n  = oid & (TN-1);
    int pc = oid >> 15;
    const float* r = g_rel + pc*RELSTRIDE + n;
    float a0 = 0.f, a1 = 0.f;
    #pragma unroll
    for (int j = 0; j < K1; j++){
        float v = r[K1-1-j];
        if (j & 1) a1 = fmaf(skg[j], v, a1);
        else       a0 = fmaf(skg[j], v, a0);
    }
    out[oid] = a0 + a1;
}

extern "C" void kernel_launch(void* const* d_in, const int* in_sizes, int n_in,
                              void* d_out, int out_size){
    (void)in_sizes; (void)n_in; (void)out_size;
    const float* x  = (const float*)d_in[0];
    const float* sb = (const float*)d_in[1];
    const float* ss = (const float*)d_in[2];

    setup_kernel<<<1, 64>>>((const float*)d_in[3]);
    xp_kernel<<<(XPLEN+255)/256, 256>>>(x, sb, ss);
    drive_kernel<<<(NSTEPS+127)/128, 128>>>();
    scan_kernel<<<2, 32>>>(
        (const float*)d_in[4],  (const float*)d_in[5],
        (const float*)d_in[6],  (const float*)d_in[7],
        (const float*)d_in[8],  (const float*)d_in[9],
        (const float*)d_in[10], (const float*)d_in[11],
        (const float*)d_in[12], (const float*)d_in[13],
        (const float*)d_in[14], (const float*)d_in[15],
        (const float*)d_in[16], (const float*)d_in[17],
        (const float*)d_in[18], (const float*)d_in[19],
        (const float*)d_in[20], (const float*)d_in[21],
        (const float*)d_in[22], (const float*)d_in[23],
        (const float*)d_in[24], (const float*)d_in[25]);
    out_kernel<<<(2*NBC*TN+255)/256, 256>>>((float*)d_out);
}

// round 9
// speedup vs baseline: 1.7682x; 1.0172x over previous
#include <cuda_runtime.h>
#include <cstdint>

#define TN 32768
#define TLOOP 32799
#define NCHUNK 2050
#define NSTEPS (NCHUNK*16)   /* 32800 */
#define NBC 14
#define NACL 10
#define NACG 35
#define KACN 52
#define K0 20
#define K1 32
#define PADL 50              /* (K0-1)+(K1-1) */
#define XPLEN (TN + PADL)    /* 32818 */
#define RELSTRIDE 32832
#define FULLM 0xffffffffu

__device__ float g_xp[XPLEN];
__device__ float g_drive[NSTEPS*NBC];
__device__ float g_rel[2*NBC*RELSTRIDE];
__device__ float g_kbc[NBC*K0];
__device__ float g_kglu[K1];

__device__ __forceinline__ float ftanh(float x){
    float y; asm("tanh.approx.f32 %0, %1;" : "=f"(y) : "f"(x)); return y;
}
__device__ __forceinline__ float fex2(float x){
    float y; asm("ex2.approx.f32 %0, %1;" : "=f"(y) : "f"(x)); return y;
}
__device__ __forceinline__ float frcp(float x){
    float y; asm("rcp.approx.f32 %0, %1;" : "=f"(y) : "f"(x)); return y;
}
/* ---- packed fp32x2 ops (FFMA2 path, full fp32 precision) ---- */
__device__ __forceinline__ uint64_t pk(float lo, float hi){
    uint64_t r; asm("mov.b64 %0, {%1,%2};" : "=l"(r) : "f"(lo), "f"(hi)); return r;
}
__device__ __forceinline__ void upk(uint64_t v, float &lo, float &hi){
    asm("mov.b64 {%0,%1}, %2;" : "=f"(lo), "=f"(hi) : "l"(v));
}
__device__ __forceinline__ uint64_t fma2(uint64_t a, uint64_t b, uint64_t c){
    uint64_t d; asm("fma.rn.f32x2 %0, %1, %2, %3;" : "=l"(d) : "l"(a), "l"(b), "l"(c)); return d;
}
__device__ __forceinline__ uint64_t mul2(uint64_t a, uint64_t b){
    uint64_t d; asm("mul.rn.f32x2 %0, %1, %2;" : "=l"(d) : "l"(a), "l"(b)); return d;
}
__device__ __forceinline__ uint64_t add2(uint64_t a, uint64_t b){
    uint64_t d; asm("add.rn.f32x2 %0, %1, %2;" : "=l"(d) : "l"(a), "l"(b)); return d;
}
/* ---- ordered shared-memory ops (warp-synchronous broadcast, no barrier):
   producer STS sits at a warp-CONVERGED point (branch-free slot-select); the
   in-order smem pipe of a single warp guarantees later LDS sees it; the
   asm volatile + memory clobbers pin compiler ordering. ---- */
__device__ __forceinline__ void sts32(float* p, float v){
    uint32_t a = (uint32_t)__cvta_generic_to_shared(p);
    asm volatile("st.shared.f32 [%0], %1;" :: "r"(a), "f"(v) : "memory");
}
__device__ __forceinline__ uint64_t ld64sv(const float* p){
    uint32_t a = (uint32_t)__cvta_generic_to_shared(p);
    uint64_t r;
    asm volatile("ld.shared.b64 %0, [%1];" : "=l"(r) : "r"(a) : "memory");
    return r;
}
__device__ __forceinline__ void ld128sv(const float* p, uint64_t &a, uint64_t &b){
    uint32_t ad = (uint32_t)__cvta_generic_to_shared(p);
    asm volatile("ld.shared.v2.u64 {%0,%1}, [%2];" : "=l"(a), "=l"(b) : "r"(ad) : "memory");
}

// double-exponential AC kernel -> IIR coefficients (exact FIR-equivalent with
// truncation correction): kern(L) = A*r1^L - B*r2^L (L=0 newest), L2-normalized
__device__ __forceinline__ void ac_coef(float ltr, float ltd,
    float &A, float &B, float &r1, float &r2, float &c1, float &c2){
    float tr = expf(ltr), td = expf(ltd);
    float beta = (td + tr) / (td * tr);
    float n2 = 0.f;
    for (int k = 0; k < KACN; k++){
        float t = 0.8f - (float)k * (1.0f/64.0f);
        float v = expf(-t/td) - expf(-beta*t);
        n2 = fmaf(v, v, n2);
    }
    float inv = 1.0f / sqrtf(n2);
    const float c0 = 0.8f - 51.0f*(1.0f/64.0f);
    A  = expf(-c0/td) * inv;
    B  = expf(-beta*c0) * inv;
    r1 = expf(-1.0f/(64.0f*td));
    r2 = expf(-beta*(1.0f/64.0f));
    c1 = expf(-0.8125f/td);        /* r1^52 */
    c2 = expf(-beta*0.8125f);      /* r2^52 */
}

// ---------------- setup: BC biphasic kernels + iGluSnFR kernel ----------------
__global__ void setup_kernel(const float* __restrict__ lks){
    int t = threadIdx.x;
    if (t < NBC){
        float speed = expf(lks[t]);
        float ct = (t < 5) ? -1.0f : 1.0f;
        float vals[K0]; float n2 = 0.f;
        #pragma unroll
        for (int j = 0; j < K0; j++){
            float ts = (float)j * (1.0f/64.0f) * speed;
            float a = ts / 0.05f, b = ts / 0.1f;
            float v = a*a*expf(-a) - 0.8f*b*b*expf(-b);
            v *= ct;
            vals[j] = v; n2 += v*v;
        }
        float inv = 1.0f / sqrtf(n2);
        #pragma unroll
        for (int j = 0; j < K0; j++) g_kbc[t*K0+j] = vals[j]*inv;
    }
    if (t == 32){
        float vals[K1]; float s = 0.f;
        #pragma unroll
        for (int j = 0; j < K1; j++){
            float tg = (float)j * (1.0f/64.0f);
            float v = (1.0f - expf(-tg/0.02f)) * expf(-tg/0.1f);
            vals[j] = v; s += v;
        }
        #pragma unroll
        for (int j = 0; j < K1; j++) g_kglu[j] = vals[j]/s;
    }
}

// ---------------- stimulus affine + edge padding ----------------
__global__ void xp_kernel(const float* __restrict__ x,
                          const float* __restrict__ sb,
                          const float* __restrict__ ss){
    int i = blockIdx.x*blockDim.x + threadIdx.x;
    if (i >= XPLEN) return;
    float es = expf(ss[0]); float b = sb[0];
    int s = i - PADL; if (s < 0) s = 0;
    g_xp[i] = x[s]*es + b;
}

// ---------------- per-BC 20-tap FIR -> drive[NSTEPS][NBC] ----------------
__global__ void drive_kernel(){
    __shared__ float skb[NBC*K0];
    int tid = threadIdx.x;
    for (int i = tid; i < NBC*K0; i += blockDim.x) skb[i] = g_kbc[i];
    __syncthreads();
    int n = blockIdx.x*blockDim.x + tid;
    if (n >= NSTEPS) return;
    if (n >= TLOOP){
        #pragma unroll
        for (int c = 0; c < NBC; c++) g_drive[n*NBC+c] = 0.f;
        return;
    }
    float xw[K0];
    #pragma unroll
    for (int j = 0; j < K0; j++) xw[j] = g_xp[n + j];
    #pragma unroll
    for (int c = 0; c < NBC; c++){
        float a0 = 0.f, a1 = 0.f;
        #pragma unroll
        for (int j = 0; j < K0; j++){
            float w = skb[c*K0+j];
            float v = xw[K0-1-j];
            if (j & 1) a1 = fmaf(w, v, a1); else a0 = fmaf(w, v, a0);
        }
        g_drive[n*NBC+c] = a0 + a1;
    }
}

// ---------------- the sequential scan: 2 blocks (pathways) x 1 warp ----------------
__global__ void __launch_bounds__(32,1) scan_kernel(
    const float* __restrict__ P_sigoff, const float* __restrict__ P_lslope,
    const float* __restrict__ P_lp01,  const float* __restrict__ P_lp12,
    const float* __restrict__ P_lipc,  const float* __restrict__ P_lrrpc,
    const float* __restrict__ P_ipst,  const float* __restrict__ P_rrpst,
    const float* __restrict__ P_laclbc, const float* __restrict__ P_lbcacl,
    const float* __restrict__ P_acltr, const float* __restrict__ P_acltd,
    const float* __restrict__ P_aclsl, const float* __restrict__ P_aclof,
    const float* __restrict__ P_lacgbc, const float* __restrict__ P_lbcacg,
    const float* __restrict__ P_acgtr, const float* __restrict__ P_acgtd,
    const float* __restrict__ P_acgsl, const float* __restrict__ P_acgof,
    const float* __restrict__ P_laclacg, const float* __restrict__ P_bcnoff)
{
    const int path = blockIdx.x;
    const int l = threadIdx.x;
    __shared__ float ringA[11*53];          /* rows 0-9 ACL, row 10 dummy */
    __shared__ float ringG[NACG*53];
    __shared__ float dbuf[2][16*NBC];
    __shared__ __align__(16) float sm_B[48];   /* [0..34] tvG/tvH, [35]=0, [36..45] tvA, [46..47] dummy */
    __shared__ __align__(16) float sm_tvA[12]; /* LNR only; [10..11] dummy */
    __shared__ __align__(16) float sm_rel[48]; /* [0..13] rel, [14..15]=0, [16..47] scratch */
    for (int i = l; i < 11*53; i += 32) ringA[i] = 0.f;
    for (int i = l; i < NACG*53; i += 32) ringG[i] = 0.f;
    { if (l < 48) sm_B[l] = 0.f; if (l+32 < 48) sm_B[l+32] = 0.f; }
    if (l < 12) sm_tvA[l] = 0.f;
    { if (l < 48) sm_rel[l] = 0.f; if (l+32 < 48) sm_rel[l+32] = 0.f; }

    const bool prim = (l < NBC);
    const int bc = prim ? l : ((l >= 16 && l < 16+NBC) ? (l-16) : -1);
    const int relSlot = prim ? l : (16 + l);          /* scratch for idle lanes */

    // ---- BC pool role (prim lanes, both paths) ----
    float cP=0.f, mBC=0.f, c_p01=0.f, c_p12=0.f, c_ipcap=0.f, c_irrp=0.f;
    float ip=0.f, rrp=0.f;
    float mh = 0.f;
    if (bc >= 0) mh = -0.5f*1.44269504f*expf(P_lslope[bc]);
    if (prim){
        float off   = P_sigoff[l] + (path ? P_bcnoff[l] : 0.f);
        mBC = 2.0f*mh;
        c_p01   = expf(P_lp01[l]);
        c_p12   = expf(P_lp12[l]);
        c_ipcap = expf(P_lipc[l]);
        float rc = expf(P_lrrpc[l]);
        c_irrp = 1.0f / rc;
        ip  = c_ipcap / (1.0f + expf(-P_ipst[l]));
        rrp = rc      / (1.0f + expf(-P_rrpst[l]));
        float sA = 0.f, sG = 0.f;
        #pragma unroll
        for (int j = 0; j < NACL; j++) sA += -expf(P_laclbc[l*NACL+j]);
        if (path){
            #pragma unroll
            for (int j = 0; j < NACG; j++) sG += -expf(P_lacgbc[l*NACG+j]);
        }
        cP = mBC*(0.5f*(sA+sG) - off);
    }

    float* relrow = g_rel + (path*NBC + (prim ? l : 0))*RELSTRIDE;
    int ri = 0;

    float fd0,fd1,fd2,fd3,fd4,fd5,fd6;
#define LOADCHUNK(k) do{ const float* _p = g_drive + (k)*224 + l; \
        fd0=_p[0]; fd1=_p[32]; fd2=_p[64]; fd3=_p[96]; fd4=_p[128]; fd5=_p[160]; fd6=_p[192]; }while(0)
#define STORECHUNK(bi) do{ float* _q = dbuf[bi] + l; \
        _q[0]=fd0; _q[32]=fd1; _q[64]=fd2; _q[96]=fd3; _q[128]=fd4; _q[160]=fd5; _q[192]=fd6; }while(0)

    if (path == 0){
        // ================= LNR pathway (rotated: tanh+STS at step tail) =================
        uint64_t wA2[5];
        #pragma unroll
        for (int k = 0; k < 5; k++) wA2[k] = 0;
        if (prim){
            #pragma unroll
            for (int k = 0; k < 5; k++){
                float w0 = -expf(P_laclbc[l*NACL+2*k]);
                float w1 = -expf(P_laclbc[l*NACL+2*k+1]);
                wA2[k] = pk(mh*w0, mh*w1);
            }
        }
        uint64_t rA2p=0, nkAc2=0, kA12p=0, wyA2[7];
        float caA=0.f, dkA=0.f;
        #pragma unroll
        for (int k = 0; k < 7; k++) wyA2[k] = 0;
        if (l < NACL){
            float A,B,r1,r2,c1,c2;
            ac_coef(P_acltr[l], P_acltd[l], A,B,r1,r2,c1,c2);
            float ha = 0.5f*expf(P_aclsl[l]);
            float kA1 = ha*A, kA2 = ha*B;
            rA2p  = pk(r1, r2);
            nkAc2 = pk(-kA1*c1, -kA2*c2);
            kA12p = pk(kA1, kA2);
            caA = -ha*P_aclof[l];
            dkA = kA1 - kA2;
            #pragma unroll
            for (int k = 0; k < 7; k++)
                wyA2[k] = pk(expf(P_lbcacl[l*NBC+2*k]), expf(P_lbcacl[l*NBC+2*k+1]));
        }
        const int tvASlot = (l < NACL) ? l : 10;
        __syncwarp();
        uint64_t A12 = 0;
        float cvA = caA;
        /* rotated prologue: stage-1 of step 0 */
        { float tv0 = ftanh(cvA); sts32(sm_tvA + tvASlot, tv0); }
        LOADCHUNK(0); STORECHUNK(0); LOADCHUNK(1);
        __syncwarp();
        for (int c = 0; c < NCHUNK; c++){
            int cur = c & 1;
            STORECHUNK(cur^1);
            int nk = (c+2 < NCHUNK) ? (c+2) : (NCHUNK-1);
            LOADCHUNK(nk);
            __syncwarp();
            const float* db = dbuf[cur];
            int tbase = c*16;
            #pragma unroll 4
            for (int i = 0; i < 16; i++){
                /* open with the broadcast LDS; fill latency with top work */
                uint64_t tp0, tp1, tp2, tp3, tp4;
                ld128sv(sm_tvA+0, tp0, tp1);
                ld128sv(sm_tvA+4, tp2, tp3);
                tp4 = ld64sv(sm_tvA+8);
                float yoA = (l < NACL) ? ringA[l*53+ri] : 0.f;
                float xi  = prim ? db[i*NBC + l] : 0.f;
                float fbBase = fmaf(mBC, xi, cP);
                float t12 = c_p12*ip*(1.0f - rrp*c_irrp);
                float ip_n = ip + c_p01*(c_ipcap - ip) - t12;
                float rrp_m = rrp + t12;
                uint64_t pbA = fma2(nkAc2, pk(yoA,yoA), mul2(rA2p, A12));
                float bA1, bA2; upk(pbA, bA1, bA2);
                float bDA = (bA1 - bA2) + caA;
                uint64_t f0 = pk(fbBase, 0.f);
                uint64_t f1 = mul2(wA2[1], tp1);
                f0 = fma2(wA2[0], tp0, f0);
                f1 = fma2(wA2[2], tp2, f1);
                f0 = fma2(wA2[3], tp3, f0);
                f1 = fma2(wA2[4], tp4, f1);
                uint64_t fs = add2(f0, f1);
                float a0,a1; upk(fs,a0,a1);
                float e = fex2(a0+a1);
                float relv = rrp * frcp(1.0f + e);
                ip = ip_n; rrp = rrp_m - relv;
                sts32(sm_rel + relSlot, relv);
                if (prim) relrow[tbase+i] = relv;
                uint64_t rp0,rp1,rp2,rp3,rp4,rp5,rp6,rpx;
                ld128sv(sm_rel+0, rp0, rp1);
                ld128sv(sm_rel+4, rp2, rp3);
                ld128sv(sm_rel+8, rp4, rp5);
                ld128sv(sm_rel+12, rp6, rpx);
                uint64_t y0 = mul2(wyA2[0], rp0);
                uint64_t y1 = mul2(wyA2[1], rp1);
                y0 = fma2(wyA2[2], rp2, y0);
                y1 = fma2(wyA2[3], rp3, y1);
                y0 = fma2(wyA2[4], rp4, y0);
                y1 = fma2(wyA2[5], rp5, y1);
                y0 = fma2(wyA2[6], rp6, y0);
                uint64_t ys = add2(y0, y1);
                float v0,v1; upk(ys,v0,v1);
                float yA = v0+v1;
                cvA = fmaf(dkA, yA, bDA);
                if (l < NACL) ringA[l*53+ri] = yA;
                A12 = fma2(kA12p, pk(yA,yA), pbA);
                /* rotated stage-1 for next step */
                float tvA = ftanh(cvA);
                sts32(sm_tvA + tvASlot, tvA);
                ri = (ri == KACN-1) ? 0 : ri+1;
            }
            __syncwarp();
        }
    } else {
        // ================= BCN pathway: rotated + vectorized broadcasts =================
        const bool isA = (l >= 16 && l < 26);
        const bool isH = (l < 3);
        // ---- G channel (every lane owns ACG channel l) ----
        uint64_t rG2p, nkGc2, kG12p, wGa2[5], wyG2[7];
        float cgG, dkG;
        {
            float A,B,r1,r2,c1,c2;
            ac_coef(P_acgtr[l], P_acgtd[l], A,B,r1,r2,c1,c2);
            float hg = 0.5f*expf(P_acgsl[l]);
            float k1 = hg*A, k2 = hg*B;
            rG2p  = pk(r1, r2);
            nkGc2 = pk(-k1*c1, -k2*c2);
            kG12p = pk(k1, k2);
            dkG = k1 - k2;
            float sw = 0.f;
            #pragma unroll
            for (int k = 0; k < 5; k++){
                float w0 = -expf(P_laclacg[l*NACL+2*k]);
                float w1 = -expf(P_laclacg[l*NACL+2*k+1]);
                sw += w0 + w1;
                wGa2[k] = pk(hg*0.5f*w0, hg*0.5f*w1);
            }
            cgG = hg*(0.5f*sw - P_acgof[l]);
            #pragma unroll
            for (int k = 0; k < 7; k++)
                wyG2[k] = pk(expf(P_lbcacg[l*NBC+2*k]), expf(P_lbcacg[l*NBC+2*k+1]));
        }
        // ---- Sec channel: A on lanes 16-25, H(=ACG 32-34) on lanes 0-2 ----
        uint64_t rS2p=0, nkSc2=0, kS12p=0, wyS2[7], wHa2[5];
        float cS=0.f, dkS=0.f;
        float* secPtr = ringA + 10*53;
        #pragma unroll
        for (int k = 0; k < 7; k++) wyS2[k] = 0;
        #pragma unroll
        for (int k = 0; k < 5; k++) wHa2[k] = 0;
        if (isA){
            int a = l - 16;
            float A,B,r1,r2,c1,c2;
            ac_coef(P_acltr[a], P_acltd[a], A,B,r1,r2,c1,c2);
            float ha = 0.5f*expf(P_aclsl[a]);
            float k1 = ha*A, k2 = ha*B;
            rS2p = pk(r1,r2); nkSc2 = pk(-k1*c1,-k2*c2); kS12p = pk(k1,k2);
            dkS = k1 - k2;
            cS = -ha*P_aclof[a];
            #pragma unroll
            for (int k = 0; k < 7; k++)
                wyS2[k] = pk(expf(P_lbcacl[a*NBC+2*k]), expf(P_lbcacl[a*NBC+2*k+1]));
            secPtr = ringA + a*53;
        } else if (isH){
            int h = l + 32;
            float A,B,r1,r2,c1,c2;
            ac_coef(P_acgtr[h], P_acgtd[h], A,B,r1,r2,c1,c2);
            float hh = 0.5f*expf(P_acgsl[h]);
            float k1 = hh*A, k2 = hh*B;
            rS2p = pk(r1,r2); nkSc2 = pk(-k1*c1,-k2*c2); kS12p = pk(k1,k2);
            dkS = k1 - k2;
            float swh = 0.f;
            #pragma unroll
            for (int k = 0; k < 5; k++){
                float w0 = -expf(P_laclacg[h*NACL+2*k]);
                float w1 = -expf(P_laclacg[h*NACL+2*k+1]);
                swh += w0 + w1;
                wHa2[k] = pk(hh*0.5f*w0, hh*0.5f*w1);
            }
            cS = hh*(0.5f*swh - P_acgof[h]);
            #pragma unroll
            for (int k = 0; k < 7; k++)
                wyS2[k] = pk(expf(P_lbcacg[h*NBC+2*k]), expf(P_lbcacg[h*NBC+2*k+1]));
            secPtr = ringG + h*53;
        }
        const int secSlot = isA ? (36 + (l-16)) : 46;
        const int hSlot   = isH ? (32 + l) : 46;
        // ---- BC feedback: ALL 36 ACG taps (35 + pad) on primary lanes, packed ----
        uint64_t wFB[18], wA2[5];
        #pragma unroll
        for (int k = 0; k < 18; k++) wFB[k] = 0;
        #pragma unroll
        for (int k = 0; k < 5; k++) wA2[k] = 0;
        if (prim){
            #pragma unroll
            for (int k = 0; k < 18; k++){
                int j0 = 2*k, j1 = 2*k+1;
                float w0 = (j0 < NACG) ? mh*(-expf(P_lacgbc[l*NACG+j0])) : 0.f;
                float w1 = (j1 < NACG) ? mh*(-expf(P_lacgbc[l*NACG+j1])) : 0.f;
                wFB[k] = pk(w0, w1);
            }
            #pragma unroll
            for (int k = 0; k < 5; k++){
                float w0 = -expf(P_laclbc[l*NACL+2*k]);
                float w1 = -expf(P_laclbc[l*NACL+2*k+1]);
                wA2[k] = pk(mh*w0, mh*w1);
            }
        }
        float* gRow = ringG + l*53;
        __syncwarp();

        uint64_t S12 = 0, G12 = 0;
        float cvS = cS, baseG = cgG;
        /* rotated prologue: stage-1 of step 0 */
        { float tv0 = ftanh(cvS); sts32(sm_B + secSlot, tv0); }
        LOADCHUNK(0); STORECHUNK(0); LOADCHUNK(1);
        __syncwarp();
        for (int c = 0; c < NCHUNK; c++){
            int cur = c & 1;
            STORECHUNK(cur^1);
            int nk = (c+2 < NCHUNK) ? (c+2) : (NCHUNK-1);
            LOADCHUNK(nk);
            __syncwarp();
            const float* db = dbuf[cur];
            int tbase = c*16;
            #pragma unroll 2
            for (int i = 0; i < 16; i++){
                /* ---- open with tvA broadcast LDS; fill with off-chain top ---- */
                uint64_t t0,t1,t2,t3,t4;
                ld128sv(sm_B+36, t0, t1);
                ld128sv(sm_B+40, t2, t3);
                t4 = ld64sv(sm_B+44);
                float yoS = secPtr[ri];
                float yoG = gRow[ri];
                float xi  = prim ? db[i*NBC + l] : 0.f;
                float fbBase = fmaf(mBC, xi, cP);
                float t12 = c_p12*ip*(1.0f - rrp*c_irrp);
                float ip_n = ip + c_p01*(c_ipcap - ip) - t12;
                float rrp_m = rrp + t12;
                uint64_t pbS = fma2(nkSc2, pk(yoS,yoS), mul2(rS2p, S12));
                uint64_t pbG = fma2(nkGc2, pk(yoG,yoG), mul2(rG2p, G12));
                float b1,b2; upk(pbS,b1,b2); float bDS = (b1-b2)+cS;
                upk(pbG,b1,b2); float bDG = (b1-b2)+cgG;
                /* ---- stage 2: ACG pre-activations from tvA ---- */
                uint64_t pg0 = pk(baseG, 0.f);
                uint64_t pg1 = mul2(wGa2[1], t1);
                pg0 = fma2(wGa2[0], t0, pg0);
                pg1 = fma2(wGa2[2], t2, pg1);
                pg0 = fma2(wGa2[3], t3, pg0);
                pg1 = fma2(wGa2[4], t4, pg1);
                uint64_t ph0 = pk(cvS, 0.f);
                uint64_t ph1 = mul2(wHa2[1], t1);
                ph0 = fma2(wHa2[0], t0, ph0);
                ph1 = fma2(wHa2[2], t2, ph1);
                ph0 = fma2(wHa2[3], t3, ph0);
                ph1 = fma2(wHa2[4], t4, ph1);
                uint64_t pgs = add2(pg0, pg1);
                uint64_t phs = add2(ph0, ph1);
                float x0,x1;
                upk(pgs,x0,x1);
                float tvG = ftanh(x0+x1);
                upk(phs,x0,x1);
                float tvH = ftanh(x0+x1);
                sts32(sm_B + l, tvG);                   /* converged */
                sts32(sm_B + hSlot, tvH);               /* converged */
                /* ---- fill tvG LDS shadow with ACL->BC partials (reuse t regs) ---- */
                uint64_t q0,q1,q2,q3,q4,q5,q6,q7,q8,q9,q10,q11,q12,q13,q14,q15,q16,q17;
                ld128sv(sm_B+0,  q0,  q1);
                ld128sv(sm_B+4,  q2,  q3);
                ld128sv(sm_B+8,  q4,  q5);
                ld128sv(sm_B+12, q6,  q7);
                ld128sv(sm_B+16, q8,  q9);
                uint64_t ae0 = mul2(wA2[0], t0);
                uint64_t ae1 = mul2(wA2[1], t1);
                ae0 = fma2(wA2[2], t2, ae0);
                ae1 = fma2(wA2[3], t3, ae1);
                ae0 = fma2(wA2[4], t4, ae0);
                ld128sv(sm_B+20, q10, q11);
                ld128sv(sm_B+24, q12, q13);
                ld128sv(sm_B+28, q14, q15);
                ld128sv(sm_B+32, q16, q17);
                /* ---- stage 3: 18 packed taps, 4 accums ---- */
                uint64_t s0 = pk(fbBase, 0.f);
                uint64_t s1 = ae0;
                uint64_t s2 = ae1;
                uint64_t s3 = mul2(wFB[3], q3);
                s0 = fma2(wFB[0], q0, s0);
                s1 = fma2(wFB[1], q1, s1);
                s2 = fma2(wFB[2], q2, s2);
                s0 = fma2(wFB[4], q4, s0);
                s1 = fma2(wFB[5], q5, s1);
                s2 = fma2(wFB[6], q6, s2);
                s3 = fma2(wFB[7], q7, s3);
                s0 = fma2(wFB[8], q8, s0);
                s1 = fma2(wFB[9], q9, s1);
                s2 = fma2(wFB[10], q10, s2);
                s3 = fma2(wFB[11], q11, s3);
                s0 = fma2(wFB[12], q12, s0);
                s1 = fma2(wFB[13], q13, s1);
                s2 = fma2(wFB[14], q14, s2);
                s3 = fma2(wFB[15], q15, s3);
                s0 = fma2(wFB[16], q16, s0);
                s1 = fma2(wFB[17], q17, s1);
                uint64_t sv = add2(add2(s0,s1), add2(s2,s3));
                float u0,u1; upk(sv,u0,u1);
                float e = fex2(u0+u1);
                float relv = rrp * frcp(1.0f + e);
                ip = ip_n; rrp = rrp_m - relv;
                sts32(sm_rel + relSlot, relv);          /* converged */
                if (prim) relrow[tbase+i] = relv;       /* divergent AFTER sts */
                /* ---- stage 4: two packed matvecs ---- */
                uint64_t rp0,rp1,rp2,rp3,rp4,rp5,rp6,rpx;
                ld128sv(sm_rel+0, rp0, rp1);
                ld128sv(sm_rel+4, rp2, rp3);
                ld128sv(sm_rel+8, rp4, rp5);
                ld128sv(sm_rel+12, rp6, rpx);
                uint64_t ga = mul2(wyG2[0], rp0);
                uint64_t gb = mul2(wyG2[1], rp1);
                ga = fma2(wyG2[2], rp2, ga);
                gb = fma2(wyG2[3], rp3, gb);
                ga = fma2(wyG2[4], rp4, ga);
                gb = fma2(wyG2[5], rp5, gb);
                ga = fma2(wyG2[6], rp6, ga);
                uint64_t sa = mul2(wyS2[0], rp0);
                uint64_t sb = mul2(wyS2[1], rp1);
                sa = fma2(wyS2[2], rp2, sa);
                sb = fma2(wyS2[3], rp3, sb);
                sa = fma2(wyS2[4], rp4, sa);
                sb = fma2(wyS2[5], rp5, sb);
                sa = fma2(wyS2[6], rp6, sa);
                uint64_t gs = add2(ga, gb);
                uint64_t ss2 = add2(sa, sb);
                float v0,v1; upk(ss2,v0,v1);
                float yS = v0+v1;
                upk(gs,v0,v1);
                float yG = v0+v1;
                cvS   = fmaf(dkS, yS, bDS);
                baseG = fmaf(dkG, yG, bDG);
                gRow[ri] = yG;
                secPtr[ri] = yS;
                S12 = fma2(kS12p, pk(yS,yS), pbS);
                G12 = fma2(kG12p, pk(yG,yG), pbG);
                /* ---- rotated stage 1 for next step ---- */
                float tvS = ftanh(cvS);
                sts32(sm_B + secSlot, tvS);
                ri = (ri == KACN-1) ? 0 : ri+1;
            }
            __syncwarp();
        }
    }
#undef LOADCHUNK
#undef STORECHUNK
}

// ---------------- iGluSnFR readout: 32-tap FIR over rel ----------------
__global__ void out_kernel(float* __restrict__ out){
    __shared__ float skg[K1];
    int tid = threadIdx.x;
    if (tid < K1) skg[tid] = g_kglu[tid];
    __syncthreads();
    int oid = blockIdx.x*blockDim.x + tid;
    if (oid >= 2*NBC*TN) return;
    int n  = oid & (TN-1);
    int pc = oid >> 15;
    const float* r = g_rel + pc*RELSTRIDE + n;
    float a0 = 0.f, a1 = 0.f;
    #pragma unroll
    for (int j = 0; j < K1; j++){
        float v = r[K1-1-j];
        if (j & 1) a1 = fmaf(skg[j], v, a1);
        else       a0 = fmaf(skg[j], v, a0);
    }
    out[oid] = a0 + a1;
}

extern "C" void kernel_launch(void* const* d_in, const int* in_sizes, int n_in,
                              void* d_out, int out_size){
    (void)in_sizes; (void)n_in; (void)out_size;
    const float* x  = (const float*)d_in[0];
    const float* sb = (const float*)d_in[1];
    const float* ss = (const float*)d_in[2];

    setup_kernel<<<1, 64>>>((const float*)d_in[3]);
    xp_kernel<<<(XPLEN+255)/256, 256>>>(x, sb, ss);
    drive_kernel<<<(NSTEPS+127)/128, 128>>>();
    scan_kernel<<<2, 32>>>(
        (const float*)d_in[4],  (const float*)d_in[5],
        (const float*)d_in[6],  (const float*)d_in[7],
        (const float*)d_in[8],  (const float*)d_in[9],
        (const float*)d_in[10], (const float*)d_in[11],
        (const float*)d_in[12], (const float*)d_in[13],
        (const float*)d_in[14], (const float*)d_in[15],
        (const float*)d_in[16], (const float*)d_in[17],
        (const float*)d_in[18], (const float*)d_in[19],
        (const float*)d_in[20], (const float*)d_in[21],
        (const float*)d_in[22], (const float*)d_in[23],
        (const float*)d_in[24], (const float*)d_in[25]);
    out_kernel<<<(2*NBC*TN+255)/256, 256>>>((float*)d_out);
}

// round 11
// speedup vs baseline: 2.0665x; 1.1687x over previous
#include <cuda_runtime.h>
#include <cstdint>

#define TN 32768
#define TLOOP 32799
#define NCHUNK 2050
#define NSTEPS (NCHUNK*16)   /* 32800 */
#define NBC 14
#define NACL 10
#define NACG 35
#define KACN 52
#define K0 20
#define K1 32
#define PADL 50              /* (K0-1)+(K1-1) */
#define XPLEN (TN + PADL)    /* 32818 */
#define RELSTRIDE 32832
#define FULLM 0xffffffffu

__device__ float g_xp[XPLEN];
__device__ float g_drive[NSTEPS*NBC];
__device__ float g_rel[2*NBC*RELSTRIDE];
__device__ float g_kbc[NBC*K0];
__device__ float g_kglu[K1];

__device__ __forceinline__ float ftanh(float x){
    float y; asm("tanh.approx.f32 %0, %1;" : "=f"(y) : "f"(x)); return y;
}
/* ---- packed fp32x2 ops (FFMA2 path, full fp32 precision) ---- */
__device__ __forceinline__ uint64_t pk(float lo, float hi){
    uint64_t r; asm("mov.b64 %0, {%1,%2};" : "=l"(r) : "f"(lo), "f"(hi)); return r;
}
__device__ __forceinline__ void upk(uint64_t v, float &lo, float &hi){
    asm("mov.b64 {%0,%1}, %2;" : "=f"(lo), "=f"(hi) : "l"(v));
}
__device__ __forceinline__ uint64_t fma2(uint64_t a, uint64_t b, uint64_t c){
    uint64_t d; asm("fma.rn.f32x2 %0, %1, %2, %3;" : "=l"(d) : "l"(a), "l"(b), "l"(c)); return d;
}
__device__ __forceinline__ uint64_t mul2(uint64_t a, uint64_t b){
    uint64_t d; asm("mul.rn.f32x2 %0, %1, %2;" : "=l"(d) : "l"(a), "l"(b)); return d;
}
__device__ __forceinline__ uint64_t add2(uint64_t a, uint64_t b){
    uint64_t d; asm("add.rn.f32x2 %0, %1, %2;" : "=l"(d) : "l"(a), "l"(b)); return d;
}
/* ---- ordered shared-memory ops (warp-synchronous broadcast, no barrier):
   producer STS sits at a warp-CONVERGED point (branch-free slot-select); the
   in-order smem pipe of a single warp guarantees later LDS sees it. ---- */
__device__ __forceinline__ void sts32(float* p, float v){
    uint32_t a = (uint32_t)__cvta_generic_to_shared(p);
    asm volatile("st.shared.f32 [%0], %1;" :: "r"(a), "f"(v) : "memory");
}
__device__ __forceinline__ uint64_t ld64sv(const float* p){
    uint32_t a = (uint32_t)__cvta_generic_to_shared(p);
    uint64_t r;
    asm volatile("ld.shared.b64 %0, [%1];" : "=l"(r) : "r"(a) : "memory");
    return r;
}
__device__ __forceinline__ void ld128sv(const float* p, uint64_t &a, uint64_t &b){
    uint32_t ad = (uint32_t)__cvta_generic_to_shared(p);
    asm volatile("ld.shared.v2.u64 {%0,%1}, [%2];" : "=l"(a), "=l"(b) : "r"(ad) : "memory");
}

// double-exponential AC kernel -> IIR coefficients (exact FIR-equivalent with
// truncation correction): kern(L) = A*r1^L - B*r2^L (L=0 newest), L2-normalized
__device__ __forceinline__ void ac_coef(float ltr, float ltd,
    float &A, float &B, float &r1, float &r2, float &c1, float &c2){
    float tr = expf(ltr), td = expf(ltd);
    float beta = (td + tr) / (td * tr);
    float n2 = 0.f;
    for (int k = 0; k < KACN; k++){
        float t = 0.8f - (float)k * (1.0f/64.0f);
        float v = expf(-t/td) - expf(-beta*t);
        n2 = fmaf(v, v, n2);
    }
    float inv = 1.0f / sqrtf(n2);
    const float c0 = 0.8f - 51.0f*(1.0f/64.0f);
    A  = expf(-c0/td) * inv;
    B  = expf(-beta*c0) * inv;
    r1 = expf(-1.0f/(64.0f*td));
    r2 = expf(-beta*(1.0f/64.0f));
    c1 = expf(-0.8125f/td);        /* r1^52 */
    c2 = expf(-beta*0.8125f);      /* r2^52 */
}

// ---------------- setup: BC biphasic kernels + iGluSnFR kernel ----------------
__global__ void setup_kernel(const float* __restrict__ lks){
    int t = threadIdx.x;
    if (t < NBC){
        float speed = expf(lks[t]);
        float ct = (t < 5) ? -1.0f : 1.0f;
        float vals[K0]; float n2 = 0.f;
        #pragma unroll
        for (int j = 0; j < K0; j++){
            float ts = (float)j * (1.0f/64.0f) * speed;
            float a = ts / 0.05f, b = ts / 0.1f;
            float v = a*a*expf(-a) - 0.8f*b*b*expf(-b);
            v *= ct;
            vals[j] = v; n2 += v*v;
        }
        float inv = 1.0f / sqrtf(n2);
        #pragma unroll
        for (int j = 0; j < K0; j++) g_kbc[t*K0+j] = vals[j]*inv;
    }
    if (t == 32){
        float vals[K1]; float s = 0.f;
        #pragma unroll
        for (int j = 0; j < K1; j++){
            float tg = (float)j * (1.0f/64.0f);
            float v = (1.0f - expf(-tg/0.02f)) * expf(-tg/0.1f);
            vals[j] = v; s += v;
        }
        #pragma unroll
        for (int j = 0; j < K1; j++) g_kglu[j] = vals[j]/s;
    }
}

// ---------------- stimulus affine + edge padding ----------------
__global__ void xp_kernel(const float* __restrict__ x,
                          const float* __restrict__ sb,
                          const float* __restrict__ ss){
    int i = blockIdx.x*blockDim.x + threadIdx.x;
    if (i >= XPLEN) return;
    float es = expf(ss[0]); float b = sb[0];
    int s = i - PADL; if (s < 0) s = 0;
    g_xp[i] = x[s]*es + b;
}

// ---------------- per-BC 20-tap FIR -> drive[NSTEPS][NBC] ----------------
__global__ void drive_kernel(){
    __shared__ float skb[NBC*K0];
    int tid = threadIdx.x;
    for (int i = tid; i < NBC*K0; i += blockDim.x) skb[i] = g_kbc[i];
    __syncthreads();
    int n = blockIdx.x*blockDim.x + tid;
    if (n >= NSTEPS) return;
    if (n >= TLOOP){
        #pragma unroll
        for (int c = 0; c < NBC; c++) g_drive[n*NBC+c] = 0.f;
        return;
    }
    float xw[K0];
    #pragma unroll
    for (int j = 0; j < K0; j++) xw[j] = g_xp[n + j];
    #pragma unroll
    for (int c = 0; c < NBC; c++){
        float a0 = 0.f, a1 = 0.f;
        #pragma unroll
        for (int j = 0; j < K0; j++){
            float w = skb[c*K0+j];
            float v = xw[K0-1-j];
            if (j & 1) a1 = fmaf(w, v, a1); else a0 = fmaf(w, v, a0);
        }
        g_drive[n*NBC+c] = a0 + a1;
    }
}

// ---------------- the sequential scan: 2 blocks (pathways) x 1 warp ----------------
__global__ void __launch_bounds__(32,1) scan_kernel(
    const float* __restrict__ P_sigoff, const float* __restrict__ P_lslope,
    const float* __restrict__ P_lp01,  const float* __restrict__ P_lp12,
    const float* __restrict__ P_lipc,  const float* __restrict__ P_lrrpc,
    const float* __restrict__ P_ipst,  const float* __restrict__ P_rrpst,
    const float* __restrict__ P_laclbc, const float* __restrict__ P_lbcacl,
    const float* __restrict__ P_acltr, const float* __restrict__ P_acltd,
    const float* __restrict__ P_aclsl, const float* __restrict__ P_aclof,
    const float* __restrict__ P_lacgbc, const float* __restrict__ P_lbcacg,
    const float* __restrict__ P_acgtr, const float* __restrict__ P_acgtd,
    const float* __restrict__ P_acgsl, const float* __restrict__ P_acgof,
    const float* __restrict__ P_laclacg, const float* __restrict__ P_bcnoff)
{
    const int path = blockIdx.x;
    const int l = threadIdx.x;
    __shared__ float ringA[11*53];          /* rows 0-9 ACL, row 10 dummy */
    __shared__ float ringG[NACG*53];
    __shared__ float dbuf[2][16*NBC];
    __shared__ __align__(16) float sm_B[48];   /* [0..34] tvG/tvH, [35]=0, [36..45] tvA, [46..47] dummy */
    __shared__ __align__(16) float sm_tvA[12]; /* LNR only; [10..11] dummy */
    __shared__ __align__(16) float sm_rel[48]; /* [0..13] rel, [14..15]=0, [16..47] scratch */
    for (int i = l; i < 11*53; i += 32) ringA[i] = 0.f;
    for (int i = l; i < NACG*53; i += 32) ringG[i] = 0.f;
    { if (l < 48) sm_B[l] = 0.f; if (l+32 < 48) sm_B[l+32] = 0.f; }
    if (l < 12) sm_tvA[l] = 0.f;
    { if (l < 48) sm_rel[l] = 0.f; if (l+32 < 48) sm_rel[l+32] = 0.f; }

    const bool prim = (l < NBC);
    const int bc = prim ? l : ((l >= 16 && l < 16+NBC) ? (l-16) : -1);
    const int relSlot = prim ? l : (16 + l);          /* scratch for idle lanes */

    // ---- BC pool role (prim lanes, both paths); tanh-form final sigmoid ----
    // p = 0.5 + 0.5*tanh(z/2); per-tap prefold mh = 0.25*slope, xi coeff mBC = 0.5*slope
    float cP=0.f, mBC=0.f, c_p01=0.f, c_p12=0.f, c_ipcap=0.f, c_irrp=0.f;
    float ip=0.f, rrp=0.f;
    float mh = 0.f;
    if (bc >= 0) mh = 0.25f*expf(P_lslope[bc]);
    if (prim){
        float off   = P_sigoff[l] + (path ? P_bcnoff[l] : 0.f);
        mBC = 2.0f*mh;
        c_p01   = expf(P_lp01[l]);
        c_p12   = expf(P_lp12[l]);
        c_ipcap = expf(P_lipc[l]);
        float rc = expf(P_lrrpc[l]);
        c_irrp = 1.0f / rc;
        ip  = c_ipcap / (1.0f + expf(-P_ipst[l]));
        rrp = rc      / (1.0f + expf(-P_rrpst[l]));
        float sA = 0.f, sG = 0.f;
        #pragma unroll
        for (int j = 0; j < NACL; j++) sA += -expf(P_laclbc[l*NACL+j]);
        if (path){
            #pragma unroll
            for (int j = 0; j < NACG; j++) sG += -expf(P_lacgbc[l*NACG+j]);
        }
        cP = mBC*(0.5f*(sA+sG) - off);
    }

    float* relrow = g_rel + (path*NBC + (prim ? l : 0))*RELSTRIDE;
    int ri = 0;

    float fd0,fd1,fd2,fd3,fd4,fd5,fd6;
#define LOADCHUNK(k) do{ const float* _p = g_drive + (k)*224 + l; \
        fd0=_p[0]; fd1=_p[32]; fd2=_p[64]; fd3=_p[96]; fd4=_p[128]; fd5=_p[160]; fd6=_p[192]; }while(0)
#define STORECHUNK(bi) do{ float* _q = dbuf[bi] + l; \
        _q[0]=fd0; _q[32]=fd1; _q[64]=fd2; _q[96]=fd3; _q[128]=fd4; _q[160]=fd5; _q[192]=fd6; }while(0)

    if (path == 0){
        // ================= LNR pathway (rotated, tanh-sigmoid) =================
        uint64_t wA2[5];
        #pragma unroll
        for (int k = 0; k < 5; k++) wA2[k] = 0;
        if (prim){
            #pragma unroll
            for (int k = 0; k < 5; k++){
                float w0 = -expf(P_laclbc[l*NACL+2*k]);
                float w1 = -expf(P_laclbc[l*NACL+2*k+1]);
                wA2[k] = pk(mh*w0, mh*w1);
            }
        }
        uint64_t rA2p=0, nkAc2=0, kA12p=0, wyA2[7];
        float caA=0.f, dkA=0.f;
        #pragma unroll
        for (int k = 0; k < 7; k++) wyA2[k] = 0;
        if (l < NACL){
            float A,B,r1,r2,c1,c2;
            ac_coef(P_acltr[l], P_acltd[l], A,B,r1,r2,c1,c2);
            float ha = 0.5f*expf(P_aclsl[l]);
            float kA1 = ha*A, kA2 = ha*B;
            rA2p  = pk(r1, r2);
            nkAc2 = pk(-kA1*c1, -kA2*c2);
            kA12p = pk(kA1, kA2);
            caA = -ha*P_aclof[l];
            dkA = kA1 - kA2;
            #pragma unroll
            for (int k = 0; k < 7; k++)
                wyA2[k] = pk(expf(P_lbcacl[l*NBC+2*k]), expf(P_lbcacl[l*NBC+2*k+1]));
        }
        const int tvASlot = (l < NACL) ? l : 10;
        __syncwarp();
        uint64_t A12 = 0;
        float cvA = caA;
        { float tv0 = ftanh(cvA); sts32(sm_tvA + tvASlot, tv0); }
        LOADCHUNK(0); STORECHUNK(0); LOADCHUNK(1);
        __syncwarp();
        for (int c = 0; c < NCHUNK; c++){
            int cur = c & 1;
            STORECHUNK(cur^1);
            int nk = (c+2 < NCHUNK) ? (c+2) : (NCHUNK-1);
            LOADCHUNK(nk);
            __syncwarp();
            const float* db = dbuf[cur];
            int tbase = c*16;
            #pragma unroll 4
            for (int i = 0; i < 16; i++){
                uint64_t tp0, tp1, tp2, tp3, tp4;
                ld128sv(sm_tvA+0, tp0, tp1);
                ld128sv(sm_tvA+4, tp2, tp3);
                tp4 = ld64sv(sm_tvA+8);
                float yoA = (l < NACL) ? ringA[l*53+ri] : 0.f;
                float xi  = prim ? db[i*NBC + l] : 0.f;
                float fbBase = fmaf(mBC, xi, cP);
                float rrp_h = 0.5f*rrp;
                float t12 = c_p12*ip*(1.0f - rrp*c_irrp);
                float ip_n = ip + c_p01*(c_ipcap - ip) - t12;
                float rrp_m = rrp + t12;
                uint64_t pbA = fma2(nkAc2, pk(yoA,yoA), mul2(rA2p, A12));
                float bA1, bA2; upk(pbA, bA1, bA2);
                float bDA = (bA1 - bA2) + caA;
                uint64_t f0 = pk(fbBase, 0.f);
                uint64_t f1 = mul2(wA2[1], tp1);
                f0 = fma2(wA2[0], tp0, f0);
                f1 = fma2(wA2[2], tp2, f1);
                f0 = fma2(wA2[3], tp3, f0);
                f1 = fma2(wA2[4], tp4, f1);
                uint64_t fs = add2(f0, f1);
                float a0,a1; upk(fs,a0,a1);
                float tvp = ftanh(a0+a1);
                float relv = fmaf(rrp_h, tvp, rrp_h);
                ip = ip_n; rrp = rrp_m - relv;
                sts32(sm_rel + relSlot, relv);
                if (prim) relrow[tbase+i] = relv;
                uint64_t rp0,rp1,rp2,rp3,rp4,rp5,rp6,rpx;
                ld128sv(sm_rel+0, rp0, rp1);
                ld128sv(sm_rel+4, rp2, rp3);
                ld128sv(sm_rel+8, rp4, rp5);
                ld128sv(sm_rel+12, rp6, rpx);
                uint64_t y0 = mul2(wyA2[0], rp0);
                uint64_t y1 = mul2(wyA2[1], rp1);
                y0 = fma2(wyA2[2], rp2, y0);
                y1 = fma2(wyA2[3], rp3, y1);
                y0 = fma2(wyA2[4], rp4, y0);
                y1 = fma2(wyA2[5], rp5, y1);
                y0 = fma2(wyA2[6], rp6, y0);
                uint64_t ys = add2(y0, y1);
                float v0,v1; upk(ys,v0,v1);
                float yA = v0+v1;
                cvA = fmaf(dkA, yA, bDA);
                if (l < NACL) ringA[l*53+ri] = yA;
                A12 = fma2(kA12p, pk(yA,yA), pbA);
                float tvA = ftanh(cvA);
                sts32(sm_tvA + tvASlot, tvA);
                ri = (ri == KACN-1) ? 0 : ri+1;
            }
            __syncwarp();
        }
    } else {
        // ===== BCN pathway: rotated, tanh-sigmoid, yG relocated to step head =====
        const bool isA = (l >= 16 && l < 26);
        const bool isH = (l < 3);
        // ---- G channel (every lane owns ACG channel l) ----
        uint64_t rG2p, nkGc2, kG12p, wGa2[5], wyG2[7];
        float cgG, dkG;
        {
            float A,B,r1,r2,c1,c2;
            ac_coef(P_acgtr[l], P_acgtd[l], A,B,r1,r2,c1,c2);
            float hg = 0.5f*expf(P_acgsl[l]);
            float k1 = hg*A, k2 = hg*B;
            rG2p  = pk(r1, r2);
            nkGc2 = pk(-k1*c1, -k2*c2);
            kG12p = pk(k1, k2);
            dkG = k1 - k2;
            float sw = 0.f;
            #pragma unroll
            for (int k = 0; k < 5; k++){
                float w0 = -expf(P_laclacg[l*NACL+2*k]);
                float w1 = -expf(P_laclacg[l*NACL+2*k+1]);
                sw += w0 + w1;
                wGa2[k] = pk(hg*0.5f*w0, hg*0.5f*w1);
            }
            cgG = hg*(0.5f*sw - P_acgof[l]);
            #pragma unroll
            for (int k = 0; k < 7; k++)
                wyG2[k] = pk(expf(P_lbcacg[l*NBC+2*k]), expf(P_lbcacg[l*NBC+2*k+1]));
        }
        // ---- Sec channel: A on lanes 16-25, H(=ACG 32-34) on lanes 0-2 ----
        uint64_t rS2p=0, nkSc2=0, kS12p=0, wyS2[7], wHa2[5];
        float cS=0.f, dkS=0.f;
        float* secPtr = ringA + 10*53;
        #pragma unroll
        for (int k = 0; k < 7; k++) wyS2[k] = 0;
        #pragma unroll
        for (int k = 0; k < 5; k++) wHa2[k] = 0;
        if (isA){
            int a = l - 16;
            float A,B,r1,r2,c1,c2;
            ac_coef(P_acltr[a], P_acltd[a], A,B,r1,r2,c1,c2);
            float ha = 0.5f*expf(P_aclsl[a]);
            float k1 = ha*A, k2 = ha*B;
            rS2p = pk(r1,r2); nkSc2 = pk(-k1*c1,-k2*c2); kS12p = pk(k1,k2);
            dkS = k1 - k2;
            cS = -ha*P_aclof[a];
            #pragma unroll
            for (int k = 0; k < 7; k++)
                wyS2[k] = pk(expf(P_lbcacl[a*NBC+2*k]), expf(P_lbcacl[a*NBC+2*k+1]));
            secPtr = ringA + a*53;
        } else if (isH){
            int h = l + 32;
            float A,B,r1,r2,c1,c2;
            ac_coef(P_acgtr[h], P_acgtd[h], A,B,r1,r2,c1,c2);
            float hh = 0.5f*expf(P_acgsl[h]);
            float k1 = hh*A, k2 = hh*B;
            rS2p = pk(r1,r2); nkSc2 = pk(-k1*c1,-k2*c2); kS12p = pk(k1,k2);
            dkS = k1 - k2;
            float swh = 0.f;
            #pragma unroll
            for (int k = 0; k < 5; k++){
                float w0 = -expf(P_laclacg[h*NACL+2*k]);
                float w1 = -expf(P_laclacg[h*NACL+2*k+1]);
                swh += w0 + w1;
                wHa2[k] = pk(hh*0.5f*w0, hh*0.5f*w1);
            }
            cS = hh*(0.5f*swh - P_acgof[h]);
            #pragma unroll
            for (int k = 0; k < 7; k++)
                wyS2[k] = pk(expf(P_lbcacg[h*NBC+2*k]), expf(P_lbcacg[h*NBC+2*k+1]));
            secPtr = ringG + h*53;
        }
        const int secSlot = isA ? (36 + (l-16)) : 46;
        const int hSlot   = isH ? (32 + l) : 46;
        // ---- BC feedback: 36 ACG taps (35+pad) + 10 ACL taps, prim lanes ----
        uint64_t wFB[18], wA2[5];
        #pragma unroll
        for (int k = 0; k < 18; k++) wFB[k] = 0;
        #pragma unroll
        for (int k = 0; k < 5; k++) wA2[k] = 0;
        if (prim){
            #pragma unroll
            for (int k = 0; k < 18; k++){
                int j0 = 2*k, j1 = 2*k+1;
                float w0 = (j0 < NACG) ? mh*(-expf(P_lacgbc[l*NACG+j0])) : 0.f;
                float w1 = (j1 < NACG) ? mh*(-expf(P_lacgbc[l*NACG+j1])) : 0.f;
                wFB[k] = pk(w0, w1);
            }
            #pragma unroll
            for (int k = 0; k < 5; k++){
                float w0 = -expf(P_laclbc[l*NACL+2*k]);
                float w1 = -expf(P_laclbc[l*NACL+2*k+1]);
                wA2[k] = pk(mh*w0, mh*w1);
            }
        }
        float* gRow = ringG + l*53;
        __syncwarp();

        uint64_t S12 = 0;
        float cvS = cS;
        /* carried state for relocated yG: rel regs, pbG, bDG, prev ring idx */
        uint64_t rp0c=0,rp1c=0,rp2c=0,rp3c=0,rp4c=0,rp5c=0,rp6c=0;
        uint64_t pbG_c = 0;
        float bDG_c = cgG;
        int ri_c = 0;
        { float tv0 = ftanh(cvS); sts32(sm_B + secSlot, tv0); }
        LOADCHUNK(0); STORECHUNK(0); LOADCHUNK(1);
        __syncwarp();
        for (int c = 0; c < NCHUNK; c++){
            int cur = c & 1;
            STORECHUNK(cur^1);
            int nk = (c+2 < NCHUNK) ? (c+2) : (NCHUNK-1);
            LOADCHUNK(nk);
            __syncwarp();
            const float* db = dbuf[cur];
            int tbase = c*16;
            #pragma unroll 2
            for (int i = 0; i < 16; i++){
                /* ---- head: tvA LDS opens; relocated yG fills its shadow ---- */
                uint64_t t0,t1,t2,t3,t4;
                ld128sv(sm_B+36, t0, t1);
                ld128sv(sm_B+40, t2, t3);
                t4 = ld64sv(sm_B+44);
                uint64_t ga = mul2(wyG2[0], rp0c);
                uint64_t gb = mul2(wyG2[1], rp1c);
                ga = fma2(wyG2[2], rp2c, ga);
                gb = fma2(wyG2[3], rp3c, gb);
                ga = fma2(wyG2[4], rp4c, ga);
                gb = fma2(wyG2[5], rp5c, gb);
                ga = fma2(wyG2[6], rp6c, ga);
                uint64_t gsum = add2(ga, gb);
                float gv0,gv1; upk(gsum,gv0,gv1);
                float yG = gv0+gv1;
                gRow[ri_c] = yG;
                uint64_t G12 = fma2(kG12p, pk(yG,yG), pbG_c);
                float baseG = fmaf(dkG, yG, bDG_c);
                /* ---- this step's top ---- */
                float yoS = secPtr[ri];
                float yoG = gRow[ri];
                float xi  = prim ? db[i*NBC + l] : 0.f;
                float fbBase = fmaf(mBC, xi, cP);
                float rrp_h = 0.5f*rrp;
                float t12 = c_p12*ip*(1.0f - rrp*c_irrp);
                float ip_n = ip + c_p01*(c_ipcap - ip) - t12;
                float rrp_m = rrp + t12;
                uint64_t pbS = fma2(nkSc2, pk(yoS,yoS), mul2(rS2p, S12));
                uint64_t pbG = fma2(nkGc2, pk(yoG,yoG), mul2(rG2p, G12));
                float b1,b2; upk(pbS,b1,b2); float bDS = (b1-b2)+cS;
                upk(pbG,b1,b2); float bDG = (b1-b2)+cgG;
                /* ---- stage 2: ACG pre-activations from tvA ---- */
                uint64_t pg0 = pk(baseG, 0.f);
                uint64_t pg1 = mul2(wGa2[1], t1);
                pg0 = fma2(wGa2[0], t0, pg0);
                pg1 = fma2(wGa2[2], t2, pg1);
                pg0 = fma2(wGa2[3], t3, pg0);
                pg1 = fma2(wGa2[4], t4, pg1);
                uint64_t ph0 = pk(cvS, 0.f);
                uint64_t ph1 = mul2(wHa2[1], t1);
                ph0 = fma2(wHa2[0], t0, ph0);
                ph1 = fma2(wHa2[2], t2, ph1);
                ph0 = fma2(wHa2[3], t3, ph0);
                ph1 = fma2(wHa2[4], t4, ph1);
                uint64_t pgs = add2(pg0, pg1);
                uint64_t phs = add2(ph0, ph1);
                float x0,x1;
                upk(pgs,x0,x1);
                float tvG = ftanh(x0+x1);
                upk(phs,x0,x1);
                float tvH = ftanh(x0+x1);
                sts32(sm_B + l, tvG);                   /* converged */
                sts32(sm_B + hSlot, tvH);               /* converged */
                /* ---- fill tvG LDS shadow with ACL->BC partials (reuse t regs) ---- */
                uint64_t q0,q1,q2,q3,q4,q5,q6,q7,q8,q9,q10,q11,q12,q13,q14,q15,q16,q17;
                ld128sv(sm_B+0,  q0,  q1);
                ld128sv(sm_B+4,  q2,  q3);
                ld128sv(sm_B+8,  q4,  q5);
                ld128sv(sm_B+12, q6,  q7);
                ld128sv(sm_B+16, q8,  q9);
                uint64_t ae0 = mul2(wA2[0], t0);
                uint64_t ae1 = mul2(wA2[1], t1);
                ae0 = fma2(wA2[2], t2, ae0);
                ae1 = fma2(wA2[3], t3, ae1);
                ae0 = fma2(wA2[4], t4, ae0);
                ld128sv(sm_B+20, q10, q11);
                ld128sv(sm_B+24, q12, q13);
                ld128sv(sm_B+28, q14, q15);
                ld128sv(sm_B+32, q16, q17);
                /* ---- stage 3: 18 packed taps, 4 accums ---- */
                uint64_t s0 = pk(fbBase, 0.f);
                uint64_t s1 = ae0;
                uint64_t s2 = ae1;
                uint64_t s3 = mul2(wFB[3], q3);
                s0 = fma2(wFB[0], q0, s0);
                s1 = fma2(wFB[1], q1, s1);
                s2 = fma2(wFB[2], q2, s2);
                s0 = fma2(wFB[4], q4, s0);
                s1 = fma2(wFB[5], q5, s1);
                s2 = fma2(wFB[6], q6, s2);
                s3 = fma2(wFB[7], q7, s3);
                s0 = fma2(wFB[8], q8, s0);
                s1 = fma2(wFB[9], q9, s1);
                s2 = fma2(wFB[10], q10, s2);
                s3 = fma2(wFB[11], q11, s3);
                s0 = fma2(wFB[12], q12, s0);
                s1 = fma2(wFB[13], q13, s1);
                s2 = fma2(wFB[14], q14, s2);
                s3 = fma2(wFB[15], q15, s3);
                s0 = fma2(wFB[16], q16, s0);
                s1 = fma2(wFB[17], q17, s1);
                uint64_t sv = add2(add2(s0,s1), add2(s2,s3));
                float u0,u1; upk(sv,u0,u1);
                float tvp = ftanh(u0+u1);
                float relv = fmaf(rrp_h, tvp, rrp_h);
                ip = ip_n; rrp = rrp_m - relv;
                sts32(sm_rel + relSlot, relv);          /* converged */
                if (prim) relrow[tbase+i] = relv;       /* divergent AFTER sts */
                /* ---- tail: rel LDS into carried regs; yS matvec; tanhS ---- */
                uint64_t rpx;
                ld128sv(sm_rel+0, rp0c, rp1c);
                ld128sv(sm_rel+4, rp2c, rp3c);
                ld128sv(sm_rel+8, rp4c, rp5c);
                ld128sv(sm_rel+12, rp6c, rpx);
                uint64_t sa = mul2(wyS2[0], rp0c);
                uint64_t sb = mul2(wyS2[1], rp1c);
                sa = fma2(wyS2[2], rp2c, sa);
                sb = fma2(wyS2[3], rp3c, sb);
                sa = fma2(wyS2[4], rp4c, sa);
                sb = fma2(wyS2[5], rp5c, sb);
                sa = fma2(wyS2[6], rp6c, sa);
                uint64_t ss2 = add2(sa, sb);
                float v0,v1; upk(ss2,v0,v1);
                float yS = v0+v1;
                cvS = fmaf(dkS, yS, bDS);
                secPtr[ri] = yS;
                S12 = fma2(kS12p, pk(yS,yS), pbS);
                pbG_c = pbG; bDG_c = bDG; ri_c = ri;
                float tvS = ftanh(cvS);
                sts32(sm_B + secSlot, tvS);
                ri = (ri == KACN-1) ? 0 : ri+1;
            }
            __syncwarp();
        }
    }
#undef LOADCHUNK
#undef STORECHUNK
}

// ---------------- iGluSnFR readout: 32-tap FIR over rel ----------------
__global__ void out_kernel(float* __restrict__ out){
    __shared__ float skg[K1];
    int tid = threadIdx.x;
    if (tid < K1) skg[tid] = g_kglu[tid];
    __syncthreads();
    int oid = blockIdx.x*blockDim.x + tid;
    if (oid >= 2*NBC*TN) return;
    int n  = oid & (TN-1);
    int pc = oid >> 15;
    const float* r = g_rel + pc*RELSTRIDE + n;
    float a0 = 0.f, a1 = 0.f;
    #pragma unroll
    for (int j = 0; j < K1; j++){
        float v = r[K1-1-j];
        if (j & 1) a1 = fmaf(skg[j], v, a1);
        else       a0 = fmaf(skg[j], v, a0);
    }
    out[oid] = a0 + a1;
}

extern "C" void kernel_launch(void* const* d_in, const int* in_sizes, int n_in,
                              void* d_out, int out_size){
    (void)in_sizes; (void)n_in; (void)out_size;
    const float* x  = (const float*)d_in[0];
    const float* sb = (const float*)d_in[1];
    const float* ss = (const float*)d_in[2];

    setup_kernel<<<1, 64>>>((const float*)d_in[3]);
    xp_kernel<<<(XPLEN+255)/256, 256>>>(x, sb, ss);
    drive_kernel<<<(NSTEPS+127)/128, 128>>>();
    scan_kernel<<<2, 32>>>(
        (const float*)d_in[4],  (const float*)d_in[5],
        (const float*)d_in[6],  (const float*)d_in[7],
        (const float*)d_in[8],  (const float*)d_in[9],
        (const float*)d_in[10], (const float*)d_in[11],
        (const float*)d_in[12], (const float*)d_in[13],
        (const float*)d_in[14], (const float*)d_in[15],
        (const float*)d_in[16], (const float*)d_in[17],
        (const float*)d_in[18], (const float*)d_in[19],
        (const float*)d_in[20], (const float*)d_in[21],
        (const float*)d_in[22], (const float*)d_in[23],
        (const float*)d_in[24], (const float*)d_in[25]);
    out_kernel<<<(2*NBC*TN+255)/256, 256>>>((float*)d_out);
}